// round 7
// baseline (speedup 1.0000x reference)
#include <cuda_runtime.h>
#include <cstdint>

// Problem constants
#define NB 2
#define NL 256
#define NE 512
#define NH 8
#define ND 64   // head dim
// scale = 1/sqrt(64) = 0.125

// ---------------- device scratch (no allocations allowed) ----------------
__device__ float g_qp[NB*NL*NE];
__device__ float g_kp[NB*NL*NE];
__device__ float g_vp[NB*NL*NE];
__device__ float g_wk2[NB*NL*NH*NE];     // [b,k,h,g], pre-scaled by 1/8
__device__ float g_bias2[NB*NL*NH];      // pre-scaled by 1/8
__device__ float g_S1[NB*NH*NL*NL];      // [b,h,q,k], pre-scaled by 1/8
__device__ float g_S[NB*NL*NL*NH];       // logits, [b,q,k,h]
__device__ float g_P[NB*NH*NL*NL];       // probs, [b,h,q,k]
__device__ float g_attn[NB*NL*NE];       // [b,q, h*64+e]

// ---------------- packed f32x2 helpers ----------------
__device__ __forceinline__ unsigned long long f2pack(float lo, float hi) {
    unsigned long long r;
    asm("mov.b64 %0, {%1, %2};" : "=l"(r) : "f"(lo), "f"(hi));
    return r;
}
__device__ __forceinline__ void f2unpack(float& lo, float& hi, unsigned long long v) {
    asm("mov.b64 {%0, %1}, %2;" : "=f"(lo), "=f"(hi) : "l"(v));
}
__device__ __forceinline__ void fma2(unsigned long long& d,
                                     unsigned long long a, unsigned long long b) {
    asm("fma.rn.f32x2 %0, %1, %2, %0;" : "+l"(d) : "l"(a), "l"(b));
}

// ---------------- GEMM v4: packed-operand pipelined fp32x2 GEMM ----------------
// C[m,n] = alpha * sum_k A[m,k]*B[k,n]   (TRANS_B: B stored [n,k])  (+bias[n])
// 256 threads, BM x 64 tile, BK=16.
//   As: k-major transposed floats (m contiguous) -> A pairs read as u64 directly.
//   Bs: DUPLICATED u64 (b,b) per element -> B broadcast pairs read as u64 directly.
// Inner loop per kk: (BM=64) 3x LDS.128 + 8 FMA2 for 32 MACs/thread.
// Requires K % 16 == 0, dims multiples of tile, leading dims multiples of 4.
template<int BM, bool TRANS_B>
__device__ __forceinline__ void gemm4(
    const float* __restrict__ A, int lda,
    const float* __restrict__ Bmat, int ldb,
    float* __restrict__ C, int ldc,
    int K, float alpha, const float* __restrict__ bias)
{
    constexpr int RPT = BM / 16;          // rows per thread (4 or 8)
    constexpr int NP  = RPT / 2;          // row-pairs per thread (2 or 4)
    __shared__ float As[2][16][BM + 4];
    __shared__ unsigned long long Bs[2][16][64];   // duplicated (b,b)

    const int tid = threadIdx.x;          // 256 threads
    const int tx = tid & 15;              // n direction (4 cols)
    const int ty = tid >> 4;              // m direction (RPT rows)
    const int bm = blockIdx.y * BM;
    const int bn = blockIdx.x * 64;

    const int aRow = tid >> 2;            // 0..63
    const int aC4  = (tid & 3) * 4;
    const int bRowN = tid >> 4;           // 0..15 (k row, !TRANS)
    const int bColN = (tid & 15) * 4;

    constexpr int QM = BM / 64;           // A-load quadrants
    float4 a_reg[QM];
    float4 b_reg;

    auto ldg = [&](int k0) {
#pragma unroll
        for (int q = 0; q < QM; q++)
            a_reg[q] = *reinterpret_cast<const float4*>(
                A + (size_t)(bm + aRow + q * 64) * lda + k0 + aC4);
        if (!TRANS_B)
            b_reg = *reinterpret_cast<const float4*>(
                Bmat + (size_t)(k0 + bRowN) * ldb + bn + bColN);
        else
            b_reg = *reinterpret_cast<const float4*>(
                Bmat + (size_t)(bn + aRow) * ldb + k0 + aC4);
    };
    auto sts = [&](int p) {
#pragma unroll
        for (int q = 0; q < QM; q++) {
            As[p][aC4 + 0][aRow + q * 64] = a_reg[q].x;
            As[p][aC4 + 1][aRow + q * 64] = a_reg[q].y;
            As[p][aC4 + 2][aRow + q * 64] = a_reg[q].z;
            As[p][aC4 + 3][aRow + q * 64] = a_reg[q].w;
        }
        if (!TRANS_B) {
            ulonglong2 w0, w1;
            w0.x = f2pack(b_reg.x, b_reg.x); w0.y = f2pack(b_reg.y, b_reg.y);
            w1.x = f2pack(b_reg.z, b_reg.z); w1.y = f2pack(b_reg.w, b_reg.w);
            *reinterpret_cast<ulonglong2*>(&Bs[p][bRowN][bColN + 0]) = w0;
            *reinterpret_cast<ulonglong2*>(&Bs[p][bRowN][bColN + 2]) = w1;
        } else {
            Bs[p][aC4 + 0][aRow] = f2pack(b_reg.x, b_reg.x);
            Bs[p][aC4 + 1][aRow] = f2pack(b_reg.y, b_reg.y);
            Bs[p][aC4 + 2][aRow] = f2pack(b_reg.z, b_reg.z);
            Bs[p][aC4 + 3][aRow] = f2pack(b_reg.w, b_reg.w);
        }
    };

    unsigned long long acc[NP][4];
#pragma unroll
    for (int pi = 0; pi < NP; pi++)
#pragma unroll
        for (int j = 0; j < 4; j++) acc[pi][j] = 0ull;

    const int niter = K / 16;
    ldg(0);
    sts(0);
    __syncthreads();

    int p = 0;
    unsigned long long afr[2][NP];
    unsigned long long bfr[2][4];

    auto ldfrag = [&](int kk, int fb) {
#pragma unroll
        for (int q = 0; q < NP; q += 2) {
            ulonglong2 av = *reinterpret_cast<const ulonglong2*>(
                &As[p][kk][ty * RPT + q * 4]);
            afr[fb][q + 0] = av.x;
            afr[fb][q + 1] = av.y;
        }
        ulonglong2 b0 = *reinterpret_cast<const ulonglong2*>(&Bs[p][kk][tx * 4 + 0]);
        ulonglong2 b1 = *reinterpret_cast<const ulonglong2*>(&Bs[p][kk][tx * 4 + 2]);
        bfr[fb][0] = b0.x; bfr[fb][1] = b0.y;
        bfr[fb][2] = b1.x; bfr[fb][3] = b1.y;
    };
    auto comp = [&](int fb) {
#pragma unroll
        for (int j = 0; j < 4; j++)
#pragma unroll
            for (int pi = 0; pi < NP; pi++)
                fma2(acc[pi][j], afr[fb][pi], bfr[fb][j]);
    };

    for (int it = 0; it < niter; ++it) {
        if (it + 1 < niter) ldg((it + 1) * 16);   // global prefetch in flight
        ldfrag(0, 0);
#pragma unroll
        for (int kk = 0; kk < 16; kk++) {
            if (kk + 1 < 16) ldfrag(kk + 1, (kk + 1) & 1);  // frag pipeline
            comp(kk & 1);
        }
        if (it + 1 < niter) {
            sts(p ^ 1);
            __syncthreads();
            p ^= 1;
        }
    }

    // epilogue: acc[pi] holds rows (bm + ty*RPT + pi*2) [lo] and +1 [hi]
#pragma unroll
    for (int pi = 0; pi < NP; pi++) {
        const int r0 = bm + ty * RPT + pi * 2;
        const int col = bn + tx * 4;
        float lo[4], hi[4];
#pragma unroll
        for (int j = 0; j < 4; j++) f2unpack(lo[j], hi[j], acc[pi][j]);
        float4 v0, v1;
        v0.x = lo[0] * alpha; v0.y = lo[1] * alpha; v0.z = lo[2] * alpha; v0.w = lo[3] * alpha;
        v1.x = hi[0] * alpha; v1.y = hi[1] * alpha; v1.z = hi[2] * alpha; v1.w = hi[3] * alpha;
        if (bias) {
            const float* bp = bias + col;
            v0.x += bp[0]; v0.y += bp[1]; v0.z += bp[2]; v0.w += bp[3];
            v1.x += bp[0]; v1.y += bp[1]; v1.z += bp[2]; v1.w += bp[3];
        }
        *reinterpret_cast<float4*>(C + (size_t)r0 * ldc + col) = v0;
        *reinterpret_cast<float4*>(C + (size_t)(r0 + 1) * ldc + col) = v1;
    }
}

// ---------------- K1: projections qp = query@Wq, kp = key@Wk, vp = value@Wq ----------------
__global__ void __launch_bounds__(256) k_proj(
    const float* __restrict__ q, const float* __restrict__ k,
    const float* __restrict__ v,
    const float* __restrict__ Wq, const float* __restrict__ Wk)
{
    int z = blockIdx.z;
    const float* A = (z == 0) ? q : (z == 1) ? k : v;
    const float* W = (z == 1) ? Wk : Wq;   // value uses Wq (bug preserved from source)
    float* C = (z == 0) ? g_qp : (z == 1) ? g_kp : g_vp;
    gemm4<64, false>(A, NE, W, NE, C, NE, NE, 1.0f, nullptr);
}

// ---------------- K2 (merged): wk2 (z<8), S1 (z in 8..23), bias2 (z==24) ----------------
__global__ void __launch_bounds__(256) k_mid(
    const float* __restrict__ Wr, const float* __restrict__ br)
{
    const int z = blockIdx.z;
    if (z < 8) {
        // Wk2[b,k,h,:] = (1/8) * kp_head(b,k,h,:) @ Wr[h*64:(h+1)*64, :]
        const int h = z;
        gemm4<64, false>(g_kp + h * ND, NE,
                         Wr + (size_t)h * ND * NE, NE,
                         g_wk2 + (size_t)h * NE, NH * NE,
                         ND, 0.125f, nullptr);
    } else if (z < 24) {
        // S1[b,h,q,k] = (1/8) * qp_h @ kp_h^T
        if (blockIdx.x >= 4 || blockIdx.y >= 4) return;
        const int zz = z - 8;            // b*NH + h
        const int b = zz >> 3, h = zz & 7;
        gemm4<64, true>(g_qp + (size_t)b * NL * NE + h * ND, NE,
                        g_kp + (size_t)b * NL * NE + h * ND, NE,
                        g_S1 + (size_t)zz * NL * NL, NL,
                        ND, 0.125f, nullptr);
    } else {
        // bias2[b,k,h] = (1/8) * dot(br_head, kp_head)
        const int blk = blockIdx.y * 8 + blockIdx.x;
        if (blk >= 16) return;
        const int idx = blk * 256 + threadIdx.x;   // NB*NL*NH = 4096
        const int h = idx & (NH - 1);
        const int row = idx >> 3;
        float s = 0.f;
#pragma unroll 8
        for (int e = 0; e < ND; e++)
            s += br[h * ND + e] * g_kp[(size_t)row * NE + h * ND + e];
        g_bias2[idx] = s * 0.125f;
    }
}

// ---------------- K4: relation streaming pass ----------------
__global__ void __launch_bounds__(256, 2) k_rel(const float* __restrict__ relation)
{
    const int kpos = blockIdx.x;
    const int b = blockIdx.y;
    const int tid = threadIdx.x;
    const int warp = tid >> 5;
    const int lane = tid & 31;

    __shared__ float4 wk2s4[NH * NE / 4];   // 16 KB
    __shared__ float b2s[NH];

    {
        const float4* src = reinterpret_cast<const float4*>(
            g_wk2 + (size_t)(b * NL + kpos) * NH * NE);
        for (int i = tid; i < NH * NE / 4; i += 256) wk2s4[i] = src[i];
        if (tid < NH) b2s[tid] = g_bias2[(size_t)(b * NL + kpos) * NH + tid];
    }
    __syncthreads();

    for (int pass = 0; pass < 8; pass++) {
        const int q0 = pass * 32 + warp * 4;   // this warp: q0..q0+3

        const float4* rp0 = reinterpret_cast<const float4*>(
            relation + ((size_t)(b * NL + q0 + 0) * NL + kpos) * NE);
        const float4* rp1 = reinterpret_cast<const float4*>(
            relation + ((size_t)(b * NL + q0 + 1) * NL + kpos) * NE);
        const float4* rp2 = reinterpret_cast<const float4*>(
            relation + ((size_t)(b * NL + q0 + 2) * NL + kpos) * NE);
        const float4* rp3 = reinterpret_cast<const float4*>(
            relation + ((size_t)(b * NL + q0 + 3) * NL + kpos) * NE);

        float vals[32];   // vals[qq*8 + h]
#pragma unroll
        for (int i = 0; i < 32; i++) vals[i] = 0.f;

#pragma unroll
        for (int i128 = 0; i128 < 4; i128++) {
            float4 r0 = rp0[i128 * 32 + lane];
            float4 r1 = rp1[i128 * 32 + lane];
            float4 r2 = rp2[i128 * 32 + lane];
            float4 r3 = rp3[i128 * 32 + lane];
#pragma unroll
            for (int h = 0; h < NH; h++) {
                float4 w = wk2s4[h * 128 + i128 * 32 + lane];
                vals[0 * 8 + h] += r0.x * w.x + r0.y * w.y + r0.z * w.z + r0.w * w.w;
                vals[1 * 8 + h] += r1.x * w.x + r1.y * w.y + r1.z * w.z + r1.w * w.w;
                vals[2 * 8 + h] += r2.x * w.x + r2.y * w.y + r2.z * w.z + r2.w * w.w;
                vals[3 * 8 + h] += r3.x * w.x + r3.y * w.y + r3.z * w.z + r3.w * w.w;
            }
        }

        // transpose-reduce: lane l ends with full sum of vals[l]
#pragma unroll
        for (int off = 16; off > 0; off >>= 1) {
            bool hi = (lane & off) != 0;
#pragma unroll
            for (int i = 0; i < 16; i++) {
                if (i < off) {
                    float send = hi ? vals[i] : vals[i + off];
                    float recv = __shfl_xor_sync(0xffffffffu, send, off);
                    vals[i] = (hi ? vals[i + off] : vals[i]) + recv;
                }
            }
        }

        const int qq = lane >> 3;
        const int h = lane & 7;
        const int q = q0 + qq;
        float s1 = g_S1[(((size_t)b * NH + h) * NL + q) * NL + kpos];
        g_S[(((size_t)b * NL + q) * NL + kpos) * NH + h] = vals[0] + s1 + b2s[h];
    }
}

// ---------------- K5: softmax over k + write probs ----------------
__global__ void __launch_bounds__(256) k_softmax(float* __restrict__ a_out, int write_a)
{
    const int q = blockIdx.x;
    const int b = blockIdx.y;
    const int tid = threadIdx.x;
    const int warp = tid >> 5;   // = head
    const int lane = tid & 31;

    __shared__ float Ss[NL][NH + 1];   // padded

    const float* Srow = g_S + (size_t)(b * NL + q) * NL * NH;
    for (int i = tid; i < NL * NH / 4; i += 256) {
        float4 v = reinterpret_cast<const float4*>(Srow)[i];
        int idx = i * 4;
        int kk = idx >> 3, h0 = idx & 7;
        Ss[kk][h0] = v.x; Ss[kk][h0 + 1] = v.y;
        Ss[kk][h0 + 2] = v.z; Ss[kk][h0 + 3] = v.w;
    }
    __syncthreads();

    const int h = warp;
    float x[8];
#pragma unroll
    for (int i = 0; i < 8; i++) x[i] = Ss[lane + 32 * i][h];

    float m = x[0];
#pragma unroll
    for (int i = 1; i < 8; i++) m = fmaxf(m, x[i]);
#pragma unroll
    for (int off = 16; off > 0; off >>= 1)
        m = fmaxf(m, __shfl_xor_sync(0xffffffffu, m, off));

    float e[8], s = 0.f;
#pragma unroll
    for (int i = 0; i < 8; i++) { e[i] = __expf(x[i] - m); s += e[i]; }
#pragma unroll
    for (int off = 16; off > 0; off >>= 1)
        s += __shfl_xor_sync(0xffffffffu, s, off);
    float inv = 1.0f / s;

    float* Prow = g_P + (((size_t)b * NH + h) * NL + q) * NL;
#pragma unroll
    for (int i = 0; i < 8; i++) {
        float p = e[i] * inv;
        Prow[lane + 32 * i] = p;
        Ss[lane + 32 * i][h] = p;    // own column only
    }
    __syncthreads();

    if (write_a) {
        float* arow = a_out + (size_t)(b * NL + q) * NL * NH;
        int t = tid;
        float4 v0 = make_float4(Ss[t][0], Ss[t][1], Ss[t][2], Ss[t][3]);
        float4 v1 = make_float4(Ss[t][4], Ss[t][5], Ss[t][6], Ss[t][7]);
        reinterpret_cast<float4*>(arow + t * 8)[0] = v0;
        reinterpret_cast<float4*>(arow + t * 8)[1] = v1;
    }
}

// ---------------- K6: attn = P @ vp per (b,h) ----------------
__global__ void __launch_bounds__(256) k_attn()
{
    int z = blockIdx.z;           // b*NH + h
    int b = z >> 3, h = z & 7;
    const float* A = g_P + (size_t)z * NL * NL;              // L x L
    const float* Bw = g_vp + (size_t)b * NL * NE + h * ND;   // L x 64, ldb=NE
    float* C = g_attn + (size_t)b * NL * NE + h * ND;        // ldc=NE
    gemm4<64, false>(A, NL, Bw, NE, C, NE, NL, 1.0f, nullptr);
}

// ---------------- K7: out = attn @ Wo^T + bo ----------------
__global__ void __launch_bounds__(256) k_out(
    const float* __restrict__ Wo, const float* __restrict__ bo,
    float* __restrict__ out)
{
    gemm4<64, true>(g_attn, NE, Wo, NE, out, NE, NE, 1.0f, bo);
}

// ---------------- launch ----------------
extern "C" void kernel_launch(void* const* d_in, const int* in_sizes, int n_in,
                              void* d_out, int out_size)
{
    const float* query    = (const float*)d_in[0];
    const float* key      = (const float*)d_in[1];
    const float* value    = (const float*)d_in[2];
    const float* relation = (const float*)d_in[3];
    const float* Wq       = (const float*)d_in[4];
    const float* Wk       = (const float*)d_in[5];
    // d_in[6] = Wv — unused (source bug: value projected with Wq)
    const float* Wr       = (const float*)d_in[7];
    const float* br       = (const float*)d_in[8];
    const float* Wo       = (const float*)d_in[9];
    const float* bo       = (const float*)d_in[10];

    float* out = (float*)d_out;
    const int out_elems = NB * NL * NE;            // 262144
    const int a_elems   = NB * NL * NL * NH;       // 1048576
    int write_a = (out_size >= out_elems + a_elems) ? 1 : 0;
    float* a_out = out + out_elems;

    dim3 blk(256);
    k_proj   <<<dim3(8, 8, 3),   blk>>>(query, key, value, Wq, Wk);
    k_mid    <<<dim3(8, 8, 25),  blk>>>(Wr, br);
    k_rel    <<<dim3(NL, NB),    blk>>>(relation);
    k_softmax<<<dim3(NL, NB),    blk>>>(a_out, write_a);
    k_attn   <<<dim3(1, 4, 16),  blk>>>();
    k_out    <<<dim3(8, 8, 1),   blk>>>(Wo, bo, out);
}

// round 9
// speedup vs baseline: 1.4388x; 1.4388x over previous
#include <cuda_runtime.h>
#include <cuda_bf16.h>
#include <cstdint>

// Problem constants
#define NB 2
#define NL 256
#define NE 512
#define NH 8
#define ND 64   // head dim
// scale = 1/sqrt(64) = 0.125

// ---------------- device scratch (no allocations allowed) ----------------
__device__ float g_qp[NB*NL*NE];
__device__ float g_kp[NB*NL*NE];
__device__ float g_vp[NB*NL*NE];
__device__ float g_wk2[NB*NL*NH*NE];     // [b,k,h,g], pre-scaled by 1/8
__device__ float g_bias2[NB*NL*NH];      // pre-scaled by 1/8
__device__ float g_S1[NB*NH*NL*NL];      // [b,h,q,k], pre-scaled by 1/8
__device__ float g_S[NB*NL*NL*NH];       // logits, [b,q,k,h]
__device__ float g_P[NB*NH*NL*NL];       // probs, [b,h,q,k]
__device__ float g_attn[NB*NL*NE];       // [b,q, h*64+e]

// ---------------- warp-mma helpers (base PTX, sm_80+: valid on sm_103) ----------------
__device__ __forceinline__ uint32_t smem_addr_u32(const void* p) {
    return (uint32_t)__cvta_generic_to_shared(p);
}
__device__ __forceinline__ void ldsm4(uint32_t* r, uint32_t a) {
    asm volatile("ldmatrix.sync.aligned.m8n8.x4.shared.b16 {%0,%1,%2,%3}, [%4];"
        : "=r"(r[0]), "=r"(r[1]), "=r"(r[2]), "=r"(r[3]) : "r"(a));
}
__device__ __forceinline__ void ldsm4t(uint32_t* r, uint32_t a) {
    asm volatile("ldmatrix.sync.aligned.m8n8.x4.trans.shared.b16 {%0,%1,%2,%3}, [%4];"
        : "=r"(r[0]), "=r"(r[1]), "=r"(r[2]), "=r"(r[3]) : "r"(a));
}
__device__ __forceinline__ void mma_bf16(float* c, const uint32_t* a, const uint32_t* b) {
    asm volatile("mma.sync.aligned.m16n8k16.row.col.f32.bf16.bf16.f32 "
        "{%0,%1,%2,%3}, {%4,%5,%6,%7}, {%8,%9}, {%0,%1,%2,%3};"
        : "+f"(c[0]), "+f"(c[1]), "+f"(c[2]), "+f"(c[3])
        : "r"(a[0]), "r"(a[1]), "r"(a[2]), "r"(a[3]), "r"(b[0]), "r"(b[1]));
}

// ---------------- GEMM v5: bf16-split tensor-core GEMM ----------------
// C[m,n] = alpha * sum_k A[m,k]*B[k,n]   (TRANS_B: B stored [n,k])  (+bias[n])
// Block tile 128(m) x 64(n), 256 threads = 8 warps (4m x 2n), warp tile 32x32.
// Per 32-wide K-chunk: stage A,B split into bf16 hi/lo smem tiles, then MMA
// passes Ah*Bh + Ah*Bl + Al*Bh (AlBl dropped, ~2^-18 relative).
// Requires M % 128 == 0, N % 64 == 0, K % 32 == 0, fp32 pointers 16B-aligned.
template<bool TRANS_B>
__device__ __forceinline__ void gemm_mma(
    const float* __restrict__ A, int lda,
    const float* __restrict__ B, int ldb,
    float* __restrict__ C, int ldc,
    int K, float alpha, const float* __restrict__ bias)
{
    constexpr int SAS = 40;                  // sA row stride (elems): 80B, 16B-aligned
    constexpr int SBR = TRANS_B ? 64 : 32;   // sB rows
    constexpr int SBS = TRANS_B ? 40 : 72;   // sB row stride (80B / 144B)
    __shared__ __nv_bfloat16 sAh[128 * SAS], sAl[128 * SAS];
    __shared__ __nv_bfloat16 sBh[SBR * SBS], sBl[SBR * SBS];

    const int tid = threadIdx.x;
    const int lane = tid & 31;
    const int wid = tid >> 5;
    const int wm = wid & 3;                  // warp m index (0..3)
    const int wn = wid >> 2;                 // warp n index (0..1)
    const int bm = blockIdx.y * 128;
    const int bn = blockIdx.x * 64;

    const uint32_t sAh_b = smem_addr_u32(sAh);
    const uint32_t sAl_b = smem_addr_u32(sAl);
    const uint32_t sBh_b = smem_addr_u32(sBh);
    const uint32_t sBl_b = smem_addr_u32(sBl);

    // ldmatrix lane-address components
    const int aRowL = wm * 32 + (lane & 15);          // + mt*16
    const int aColL = (lane >> 4) * 8;                // + kk
    // B (!TRANS, [k][n], trans-ldmatrix): row k = (lane&7)+((lane>>3)&1)*8 (+kk),
    //                                     col n = wn*32 + ntp*16 + (lane>>4)*8
    // B (TRANS, [n][k], ldmatrix):        row n = wn*32 + ntp*16 + (lane&7) + (lane>>4)*8,
    //                                     col k = ((lane>>3)&1)*8 (+kk)
    const int bRowL = TRANS_B ? (wn * 32 + (lane & 7) + (lane >> 4) * 8)
                              : ((lane & 7) + ((lane >> 3) & 1) * 8);
    const int bColL = TRANS_B ? (((lane >> 3) & 1) * 8)
                              : (wn * 32 + (lane >> 4) * 8);

    float acc[2][4][4];
#pragma unroll
    for (int mt = 0; mt < 2; mt++)
#pragma unroll
        for (int nt = 0; nt < 4; nt++)
#pragma unroll
            for (int j = 0; j < 4; j++) acc[mt][nt][j] = 0.f;

    const int nchunk = K / 32;
    for (int c = 0; c < nchunk; ++c) {
        const int k0 = c * 32;

        // ---- stage A (128 x 32) split hi/lo ----
#pragma unroll
        for (int i = 0; i < 4; i++) {
            int lin = tid + i * 256;                 // 0..1023
            int row = lin >> 3, c4 = (lin & 7) * 4;
            float4 v = *reinterpret_cast<const float4*>(
                A + (size_t)(bm + row) * lda + k0 + c4);
            __nv_bfloat162 h01 = __floats2bfloat162_rn(v.x, v.y);
            __nv_bfloat162 h23 = __floats2bfloat162_rn(v.z, v.w);
            float2 f01 = __bfloat1622float2(h01);
            float2 f23 = __bfloat1622float2(h23);
            __nv_bfloat162 l01 = __floats2bfloat162_rn(v.x - f01.x, v.y - f01.y);
            __nv_bfloat162 l23 = __floats2bfloat162_rn(v.z - f23.x, v.w - f23.y);
            *reinterpret_cast<__nv_bfloat162*>(&sAh[row * SAS + c4])     = h01;
            *reinterpret_cast<__nv_bfloat162*>(&sAh[row * SAS + c4 + 2]) = h23;
            *reinterpret_cast<__nv_bfloat162*>(&sAl[row * SAS + c4])     = l01;
            *reinterpret_cast<__nv_bfloat162*>(&sAl[row * SAS + c4 + 2]) = l23;
        }
        // ---- stage B (32 x 64 or 64 x 32) split hi/lo ----
#pragma unroll
        for (int i = 0; i < 2; i++) {
            int lin = tid + i * 256;                 // 0..511
            int row, c4;
            const float* src;
            if (!TRANS_B) {
                row = lin >> 4; c4 = (lin & 15) * 4;
                src = B + (size_t)(k0 + row) * ldb + bn + c4;
            } else {
                row = lin >> 3; c4 = (lin & 7) * 4;
                src = B + (size_t)(bn + row) * ldb + k0 + c4;
            }
            float4 v = *reinterpret_cast<const float4*>(src);
            __nv_bfloat162 h01 = __floats2bfloat162_rn(v.x, v.y);
            __nv_bfloat162 h23 = __floats2bfloat162_rn(v.z, v.w);
            float2 f01 = __bfloat1622float2(h01);
            float2 f23 = __bfloat1622float2(h23);
            __nv_bfloat162 l01 = __floats2bfloat162_rn(v.x - f01.x, v.y - f01.y);
            __nv_bfloat162 l23 = __floats2bfloat162_rn(v.z - f23.x, v.w - f23.y);
            *reinterpret_cast<__nv_bfloat162*>(&sBh[row * SBS + c4])     = h01;
            *reinterpret_cast<__nv_bfloat162*>(&sBh[row * SBS + c4 + 2]) = h23;
            *reinterpret_cast<__nv_bfloat162*>(&sBl[row * SBS + c4])     = l01;
            *reinterpret_cast<__nv_bfloat162*>(&sBl[row * SBS + c4 + 2]) = l23;
        }
        __syncthreads();

#pragma unroll
        for (int kk = 0; kk < 32; kk += 16) {
            uint32_t afr[2][4], bh[8], bl[8];
            // A hi fragments (m32 x k16)
#pragma unroll
            for (int mt = 0; mt < 2; mt++) {
                uint32_t off = (uint32_t)(((aRowL + mt * 16) * SAS + aColL + kk) * 2);
                ldsm4(afr[mt], sAh_b + off);
            }
            // B hi + lo fragments (k16 x n32)
#pragma unroll
            for (int ntp = 0; ntp < 2; ntp++) {
                uint32_t off;
                if (!TRANS_B)
                    off = (uint32_t)(((bRowL + kk) * SBS + bColL + ntp * 16) * 2);
                else
                    off = (uint32_t)(((bRowL + ntp * 16) * SBS + bColL + kk) * 2);
                if (!TRANS_B) {
                    ldsm4t(&bh[ntp * 4], sBh_b + off);
                    ldsm4t(&bl[ntp * 4], sBl_b + off);
                } else {
                    ldsm4(&bh[ntp * 4], sBh_b + off);
                    ldsm4(&bl[ntp * 4], sBl_b + off);
                }
            }
            // Ah*Bh + Ah*Bl
#pragma unroll
            for (int mt = 0; mt < 2; mt++)
#pragma unroll
                for (int nt = 0; nt < 4; nt++) {
                    const uint32_t* bp = &bh[(nt >> 1) * 4 + (nt & 1) * 2];
                    const uint32_t* lp = &bl[(nt >> 1) * 4 + (nt & 1) * 2];
                    mma_bf16(acc[mt][nt], afr[mt], bp);
                    mma_bf16(acc[mt][nt], afr[mt], lp);
                }
            // Al*Bh
#pragma unroll
            for (int mt = 0; mt < 2; mt++) {
                uint32_t off = (uint32_t)(((aRowL + mt * 16) * SAS + aColL + kk) * 2);
                ldsm4(afr[mt], sAl_b + off);
            }
#pragma unroll
            for (int mt = 0; mt < 2; mt++)
#pragma unroll
                for (int nt = 0; nt < 4; nt++)
                    mma_bf16(acc[mt][nt], afr[mt], &bh[(nt >> 1) * 4 + (nt & 1) * 2]);
        }
        __syncthreads();
    }

    // ---- epilogue ----
    const int r0 = bm + wm * 32 + (lane >> 2);
    const int c0 = bn + wn * 32 + (lane & 3) * 2;
#pragma unroll
    for (int mt = 0; mt < 2; mt++)
#pragma unroll
        for (int nt = 0; nt < 4; nt++) {
            const int row = r0 + mt * 16;
            const int col = c0 + nt * 8;
            float2 v0, v1;
            v0.x = acc[mt][nt][0] * alpha; v0.y = acc[mt][nt][1] * alpha;
            v1.x = acc[mt][nt][2] * alpha; v1.y = acc[mt][nt][3] * alpha;
            if (bias) {
                v0.x += bias[col]; v0.y += bias[col + 1];
                v1.x += bias[col]; v1.y += bias[col + 1];
            }
            *reinterpret_cast<float2*>(C + (size_t)row * ldc + col) = v0;
            *reinterpret_cast<float2*>(C + (size_t)(row + 8) * ldc + col) = v1;
        }
}

// ---------------- K1: projections qp = query@Wq, kp = key@Wk, vp = value@Wq ----------------
__global__ void __launch_bounds__(256) k_proj(
    const float* __restrict__ q, const float* __restrict__ k,
    const float* __restrict__ v,
    const float* __restrict__ Wq, const float* __restrict__ Wk)
{
    int z = blockIdx.z;
    const float* A = (z == 0) ? q : (z == 1) ? k : v;
    const float* W = (z == 1) ? Wk : Wq;   // value uses Wq (bug preserved from source)
    float* C = (z == 0) ? g_qp : (z == 1) ? g_kp : g_vp;
    gemm_mma<false>(A, NE, W, NE, C, NE, NE, 1.0f, nullptr);
}

// ---------------- K2 (merged): wk2 (z<8), S1 (z in 8..23), bias2 (z==24) ----------------
__global__ void __launch_bounds__(256) k_mid(
    const float* __restrict__ Wr, const float* __restrict__ br)
{
    const int z = blockIdx.z;
    if (z < 8) {
        // Wk2[b,k,h,:] = (1/8) * kp_head(b,k,h,:) @ Wr[h*64:(h+1)*64, :]
        const int h = z;
        gemm_mma<false>(g_kp + h * ND, NE,
                        Wr + (size_t)h * ND * NE, NE,
                        g_wk2 + (size_t)h * NE, NH * NE,
                        ND, 0.125f, nullptr);
    } else if (z < 24) {
        // S1[b,h,q,k] = (1/8) * qp_h @ kp_h^T
        if (blockIdx.x >= 4 || blockIdx.y >= 2) return;
        const int zz = z - 8;            // b*NH + h
        const int b = zz >> 3, h = zz & 7;
        gemm_mma<true>(g_qp + (size_t)b * NL * NE + h * ND, NE,
                       g_kp + (size_t)b * NL * NE + h * ND, NE,
                       g_S1 + (size_t)zz * NL * NL, NL,
                       ND, 0.125f, nullptr);
    } else {
        // bias2[b,k,h] = (1/8) * dot(br_head, kp_head)
        const int blk = blockIdx.y * 8 + blockIdx.x;
        if (blk >= 16) return;
        const int idx = blk * 256 + threadIdx.x;   // NB*NL*NH = 4096
        const int h = idx & (NH - 1);
        const int row = idx >> 3;
        float s = 0.f;
#pragma unroll 8
        for (int e = 0; e < ND; e++)
            s += br[h * ND + e] * g_kp[(size_t)row * NE + h * ND + e];
        g_bias2[idx] = s * 0.125f;
    }
}

// ---------------- K4: relation streaming pass ----------------
__global__ void __launch_bounds__(256, 2) k_rel(const float* __restrict__ relation)
{
    const int kpos = blockIdx.x;
    const int b = blockIdx.y;
    const int tid = threadIdx.x;
    const int warp = tid >> 5;
    const int lane = tid & 31;

    __shared__ float4 wk2s4[NH * NE / 4];   // 16 KB
    __shared__ float b2s[NH];

    {
        const float4* src = reinterpret_cast<const float4*>(
            g_wk2 + (size_t)(b * NL + kpos) * NH * NE);
        for (int i = tid; i < NH * NE / 4; i += 256) wk2s4[i] = src[i];
        if (tid < NH) b2s[tid] = g_bias2[(size_t)(b * NL + kpos) * NH + tid];
    }
    __syncthreads();

    for (int pass = 0; pass < 8; pass++) {
        const int q0 = pass * 32 + warp * 4;   // this warp: q0..q0+3

        const float4* rp0 = reinterpret_cast<const float4*>(
            relation + ((size_t)(b * NL + q0 + 0) * NL + kpos) * NE);
        const float4* rp1 = reinterpret_cast<const float4*>(
            relation + ((size_t)(b * NL + q0 + 1) * NL + kpos) * NE);
        const float4* rp2 = reinterpret_cast<const float4*>(
            relation + ((size_t)(b * NL + q0 + 2) * NL + kpos) * NE);
        const float4* rp3 = reinterpret_cast<const float4*>(
            relation + ((size_t)(b * NL + q0 + 3) * NL + kpos) * NE);

        float vals[32];   // vals[qq*8 + h]
#pragma unroll
        for (int i = 0; i < 32; i++) vals[i] = 0.f;

#pragma unroll
        for (int i128 = 0; i128 < 4; i128++) {
            float4 r0 = rp0[i128 * 32 + lane];
            float4 r1 = rp1[i128 * 32 + lane];
            float4 r2 = rp2[i128 * 32 + lane];
            float4 r3 = rp3[i128 * 32 + lane];
#pragma unroll
            for (int h = 0; h < NH; h++) {
                float4 w = wk2s4[h * 128 + i128 * 32 + lane];
                vals[0 * 8 + h] += r0.x * w.x + r0.y * w.y + r0.z * w.z + r0.w * w.w;
                vals[1 * 8 + h] += r1.x * w.x + r1.y * w.y + r1.z * w.z + r1.w * w.w;
                vals[2 * 8 + h] += r2.x * w.x + r2.y * w.y + r2.z * w.z + r2.w * w.w;
                vals[3 * 8 + h] += r3.x * w.x + r3.y * w.y + r3.z * w.z + r3.w * w.w;
            }
        }

        // transpose-reduce: lane l ends with full sum of vals[l]
#pragma unroll
        for (int off = 16; off > 0; off >>= 1) {
            bool hi = (lane & off) != 0;
#pragma unroll
            for (int i = 0; i < 16; i++) {
                if (i < off) {
                    float send = hi ? vals[i] : vals[i + off];
                    float recv = __shfl_xor_sync(0xffffffffu, send, off);
                    vals[i] = (hi ? vals[i + off] : vals[i]) + recv;
                }
            }
        }

        const int qq = lane >> 3;
        const int h = lane & 7;
        const int q = q0 + qq;
        float s1 = g_S1[(((size_t)b * NH + h) * NL + q) * NL + kpos];
        g_S[(((size_t)b * NL + q) * NL + kpos) * NH + h] = vals[0] + s1 + b2s[h];
    }
}

// ---------------- K5: softmax over k + write probs ----------------
__global__ void __launch_bounds__(256) k_softmax(float* __restrict__ a_out, int write_a)
{
    const int q = blockIdx.x;
    const int b = blockIdx.y;
    const int tid = threadIdx.x;
    const int warp = tid >> 5;   // = head
    const int lane = tid & 31;

    __shared__ float Ss[NL][NH + 1];   // padded

    const float* Srow = g_S + (size_t)(b * NL + q) * NL * NH;
    for (int i = tid; i < NL * NH / 4; i += 256) {
        float4 v = reinterpret_cast<const float4*>(Srow)[i];
        int idx = i * 4;
        int kk = idx >> 3, h0 = idx & 7;
        Ss[kk][h0] = v.x; Ss[kk][h0 + 1] = v.y;
        Ss[kk][h0 + 2] = v.z; Ss[kk][h0 + 3] = v.w;
    }
    __syncthreads();

    const int h = warp;
    float x[8];
#pragma unroll
    for (int i = 0; i < 8; i++) x[i] = Ss[lane + 32 * i][h];

    float m = x[0];
#pragma unroll
    for (int i = 1; i < 8; i++) m = fmaxf(m, x[i]);
#pragma unroll
    for (int off = 16; off > 0; off >>= 1)
        m = fmaxf(m, __shfl_xor_sync(0xffffffffu, m, off));

    float e[8], s = 0.f;
#pragma unroll
    for (int i = 0; i < 8; i++) { e[i] = __expf(x[i] - m); s += e[i]; }
#pragma unroll
    for (int off = 16; off > 0; off >>= 1)
        s += __shfl_xor_sync(0xffffffffu, s, off);
    float inv = 1.0f / s;

    float* Prow = g_P + (((size_t)b * NH + h) * NL + q) * NL;
#pragma unroll
    for (int i = 0; i < 8; i++) {
        float p = e[i] * inv;
        Prow[lane + 32 * i] = p;
        Ss[lane + 32 * i][h] = p;    // own column only
    }
    __syncthreads();

    if (write_a) {
        float* arow = a_out + (size_t)(b * NL + q) * NL * NH;
        int t = tid;
        float4 v0 = make_float4(Ss[t][0], Ss[t][1], Ss[t][2], Ss[t][3]);
        float4 v1 = make_float4(Ss[t][4], Ss[t][5], Ss[t][6], Ss[t][7]);
        reinterpret_cast<float4*>(arow + t * 8)[0] = v0;
        reinterpret_cast<float4*>(arow + t * 8)[1] = v1;
    }
}

// ---------------- K6: attn = P @ vp per (b,h) ----------------
__global__ void __launch_bounds__(256) k_attn()
{
    int z = blockIdx.z;           // b*NH + h
    int b = z >> 3, h = z & 7;
    const float* A = g_P + (size_t)z * NL * NL;              // L x L
    const float* Bw = g_vp + (size_t)b * NL * NE + h * ND;   // L x 64, ldb=NE
    float* C = g_attn + (size_t)b * NL * NE + h * ND;        // ldc=NE
    gemm_mma<false>(A, NL, Bw, NE, C, NE, NL, 1.0f, nullptr);
}

// ---------------- K7: out = attn @ Wo^T + bo ----------------
__global__ void __launch_bounds__(256) k_out(
    const float* __restrict__ Wo, const float* __restrict__ bo,
    float* __restrict__ out)
{
    gemm_mma<true>(g_attn, NE, Wo, NE, out, NE, NE, 1.0f, bo);
}

// ---------------- launch ----------------
extern "C" void kernel_launch(void* const* d_in, const int* in_sizes, int n_in,
                              void* d_out, int out_size)
{
    const float* query    = (const float*)d_in[0];
    const float* key      = (const float*)d_in[1];
    const float* value    = (const float*)d_in[2];
    const float* relation = (const float*)d_in[3];
    const float* Wq       = (const float*)d_in[4];
    const float* Wk       = (const float*)d_in[5];
    // d_in[6] = Wv — unused (source bug: value projected with Wq)
    const float* Wr       = (const float*)d_in[7];
    const float* br       = (const float*)d_in[8];
    const float* Wo       = (const float*)d_in[9];
    const float* bo       = (const float*)d_in[10];

    float* out = (float*)d_out;
    const int out_elems = NB * NL * NE;            // 262144
    const int a_elems   = NB * NL * NL * NH;       // 1048576
    int write_a = (out_size >= out_elems + a_elems) ? 1 : 0;
    float* a_out = out + out_elems;

    dim3 blk(256);
    k_proj   <<<dim3(8, 4, 3),   blk>>>(query, key, value, Wq, Wk);
    k_mid    <<<dim3(8, 4, 25),  blk>>>(Wr, br);
    k_rel    <<<dim3(NL, NB),    blk>>>(relation);
    k_softmax<<<dim3(NL, NB),    blk>>>(a_out, write_a);
    k_attn   <<<dim3(1, 2, 16),  blk>>>();
    k_out    <<<dim3(8, 4, 1),   blk>>>(Wo, bo, out);
}

// round 10
// speedup vs baseline: 1.7037x; 1.1841x over previous
#include <cuda_runtime.h>
#include <cuda_bf16.h>
#include <cstdint>

// Problem constants
#define NB 2
#define NL 256
#define NE 512
#define NH 8
#define ND 64   // head dim
// scale = 1/sqrt(64) = 0.125

// ---------------- device scratch (no allocations allowed) ----------------
__device__ float g_qp[NB*NL*NE];
__device__ float g_kp[NB*NL*NE];
__device__ float g_vp[NB*NL*NE];
__device__ float g_wk2[NB*NL*NH*NE];     // [b,k,h,g], pre-scaled by 1/8
__device__ float g_bias2[NB*NL*NH];      // pre-scaled by 1/8
__device__ float g_S1[NB*NH*NL*NL];      // [b,h,q,k], pre-scaled by 1/8
__device__ float g_S[NB*NL*NL*NH];       // logits, [b,q,k,h]
__device__ float g_P[NB*NH*NL*NL];       // probs, [b,h,q,k]
__device__ float g_attn[NB*NL*NE];       // [b,q, h*64+e]

// ---------------- packed f32x2 helpers ----------------
__device__ __forceinline__ unsigned long long f2pack(float lo, float hi) {
    unsigned long long r;
    asm("mov.b64 %0, {%1, %2};" : "=l"(r) : "f"(lo), "f"(hi));
    return r;
}
__device__ __forceinline__ void f2unpack(float& lo, float& hi, unsigned long long v) {
    asm("mov.b64 {%0, %1}, %2;" : "=f"(lo), "=f"(hi) : "l"(v));
}
__device__ __forceinline__ void fma2(unsigned long long& d,
                                     unsigned long long a, unsigned long long b) {
    asm("fma.rn.f32x2 %0, %1, %2, %0;" : "+l"(d) : "l"(a), "l"(b));
}

// ---------------- warp-mma helpers (base PTX, sm_80+: valid on sm_103) ----------------
__device__ __forceinline__ uint32_t smem_addr_u32(const void* p) {
    return (uint32_t)__cvta_generic_to_shared(p);
}
__device__ __forceinline__ void ldsm4(uint32_t* r, uint32_t a) {
    asm volatile("ldmatrix.sync.aligned.m8n8.x4.shared.b16 {%0,%1,%2,%3}, [%4];"
        : "=r"(r[0]), "=r"(r[1]), "=r"(r[2]), "=r"(r[3]) : "r"(a));
}
__device__ __forceinline__ void ldsm4t(uint32_t* r, uint32_t a) {
    asm volatile("ldmatrix.sync.aligned.m8n8.x4.trans.shared.b16 {%0,%1,%2,%3}, [%4];"
        : "=r"(r[0]), "=r"(r[1]), "=r"(r[2]), "=r"(r[3]) : "r"(a));
}
__device__ __forceinline__ void mma_bf16(float* c, const uint32_t* a, const uint32_t* b) {
    asm volatile("mma.sync.aligned.m16n8k16.row.col.f32.bf16.bf16.f32 "
        "{%0,%1,%2,%3}, {%4,%5,%6,%7}, {%8,%9}, {%0,%1,%2,%3};"
        : "+f"(c[0]), "+f"(c[1]), "+f"(c[2]), "+f"(c[3])
        : "r"(a[0]), "r"(a[1]), "r"(a[2]), "r"(a[3]), "r"(b[0]), "r"(b[1]));
}

// ---------------- GEMM v5b: bf16-split tensor-core GEMM with LDG prefetch ----------------
// C[m,n] = alpha * sum_k A[m,k]*B[k,n]   (TRANS_B: B stored [n,k])  (+bias[n])
// Block tile 128(m) x 64(n), 256 threads = 8 warps (4m x 2n), warp tile 32x32.
// Per 32-wide K-chunk: stage A,B split into bf16 hi/lo smem tiles, then MMA
// passes Ah*Bh + Ah*Bl + Al*Bh (AlBl dropped, ~2^-18 relative).
// LDG of chunk c+1 overlaps the MMA section of chunk c.
template<bool TRANS_B>
__device__ __forceinline__ void gemm_mma(
    const float* __restrict__ A, int lda,
    const float* __restrict__ B, int ldb,
    float* __restrict__ C, int ldc,
    int K, float alpha, const float* __restrict__ bias)
{
    constexpr int SAS = 40;                  // sA row stride (elems): 80B, 16B-aligned
    constexpr int SBR = TRANS_B ? 64 : 32;   // sB rows
    constexpr int SBS = TRANS_B ? 40 : 72;   // sB row stride (80B / 144B)
    __shared__ __nv_bfloat16 sAh[128 * SAS], sAl[128 * SAS];
    __shared__ __nv_bfloat16 sBh[SBR * SBS], sBl[SBR * SBS];

    const int tid = threadIdx.x;
    const int lane = tid & 31;
    const int wid = tid >> 5;
    const int wm = wid & 3;                  // warp m index (0..3)
    const int wn = wid >> 2;                 // warp n index (0..1)
    const int bm = blockIdx.y * 128;
    const int bn = blockIdx.x * 64;

    const uint32_t sAh_b = smem_addr_u32(sAh);
    const uint32_t sAl_b = smem_addr_u32(sAl);
    const uint32_t sBh_b = smem_addr_u32(sBh);
    const uint32_t sBl_b = smem_addr_u32(sBl);

    const int aRowL = wm * 32 + (lane & 15);          // + mt*16
    const int aColL = (lane >> 4) * 8;                // + kk
    const int bRowL = TRANS_B ? (wn * 32 + (lane & 7) + (lane >> 4) * 8)
                              : ((lane & 7) + ((lane >> 3) & 1) * 8);
    const int bColL = TRANS_B ? (((lane >> 3) & 1) * 8)
                              : (wn * 32 + (lane >> 4) * 8);

    // staging indices
    const int aSRow = tid >> 3, aSC4 = (tid & 7) * 4;        // +256-thread stride: 32 rows
    const int bSRowN = tid >> 4, bSC4N = (tid & 15) * 4;     // !TRANS
    const int bSRowT = tid >> 3, bSC4T = (tid & 7) * 4;      // TRANS

    float4 aR[4], bR[2];
    auto ldg = [&](int k0) {
#pragma unroll
        for (int i = 0; i < 4; i++)
            aR[i] = *reinterpret_cast<const float4*>(
                A + (size_t)(bm + aSRow + i * 32) * lda + k0 + aSC4);
#pragma unroll
        for (int i = 0; i < 2; i++) {
            if (!TRANS_B)
                bR[i] = *reinterpret_cast<const float4*>(
                    B + (size_t)(k0 + bSRowN + i * 16) * ldb + bn + bSC4N);
            else
                bR[i] = *reinterpret_cast<const float4*>(
                    B + (size_t)(bn + bSRowT + i * 32) * ldb + k0 + bSC4T);
        }
    };
    auto split_store = [&](__nv_bfloat16* hB, __nv_bfloat16* lB, int idx, float4 v) {
        __nv_bfloat162 h01 = __floats2bfloat162_rn(v.x, v.y);
        __nv_bfloat162 h23 = __floats2bfloat162_rn(v.z, v.w);
        float2 f01 = __bfloat1622float2(h01);
        float2 f23 = __bfloat1622float2(h23);
        __nv_bfloat162 l01 = __floats2bfloat162_rn(v.x - f01.x, v.y - f01.y);
        __nv_bfloat162 l23 = __floats2bfloat162_rn(v.z - f23.x, v.w - f23.y);
        *reinterpret_cast<__nv_bfloat162*>(&hB[idx])     = h01;
        *reinterpret_cast<__nv_bfloat162*>(&hB[idx + 2]) = h23;
        *reinterpret_cast<__nv_bfloat162*>(&lB[idx])     = l01;
        *reinterpret_cast<__nv_bfloat162*>(&lB[idx + 2]) = l23;
    };
    auto sts = [&]() {
#pragma unroll
        for (int i = 0; i < 4; i++)
            split_store(sAh, sAl, (aSRow + i * 32) * SAS + aSC4, aR[i]);
#pragma unroll
        for (int i = 0; i < 2; i++) {
            int idx = (!TRANS_B) ? ((bSRowN + i * 16) * SBS + bSC4N)
                                 : ((bSRowT + i * 32) * SBS + bSC4T);
            split_store(sBh, sBl, idx, bR[i]);
        }
    };

    float acc[2][4][4];
#pragma unroll
    for (int mt = 0; mt < 2; mt++)
#pragma unroll
        for (int nt = 0; nt < 4; nt++)
#pragma unroll
            for (int j = 0; j < 4; j++) acc[mt][nt][j] = 0.f;

    const int nchunk = K / 32;
    ldg(0);
    sts();
    __syncthreads();

    for (int c = 0; c < nchunk; ++c) {
        if (c + 1 < nchunk) ldg((c + 1) * 32);   // prefetch overlaps MMAs below

#pragma unroll
        for (int kk = 0; kk < 32; kk += 16) {
            uint32_t afr[2][4], bh[8], bl[8];
#pragma unroll
            for (int mt = 0; mt < 2; mt++) {
                uint32_t off = (uint32_t)(((aRowL + mt * 16) * SAS + aColL + kk) * 2);
                ldsm4(afr[mt], sAh_b + off);
            }
#pragma unroll
            for (int ntp = 0; ntp < 2; ntp++) {
                uint32_t off;
                if (!TRANS_B)
                    off = (uint32_t)(((bRowL + kk) * SBS + bColL + ntp * 16) * 2);
                else
                    off = (uint32_t)(((bRowL + ntp * 16) * SBS + bColL + kk) * 2);
                if (!TRANS_B) {
                    ldsm4t(&bh[ntp * 4], sBh_b + off);
                    ldsm4t(&bl[ntp * 4], sBl_b + off);
                } else {
                    ldsm4(&bh[ntp * 4], sBh_b + off);
                    ldsm4(&bl[ntp * 4], sBl_b + off);
                }
            }
#pragma unroll
            for (int mt = 0; mt < 2; mt++)
#pragma unroll
                for (int nt = 0; nt < 4; nt++) {
                    const uint32_t* bp = &bh[(nt >> 1) * 4 + (nt & 1) * 2];
                    const uint32_t* lp = &bl[(nt >> 1) * 4 + (nt & 1) * 2];
                    mma_bf16(acc[mt][nt], afr[mt], bp);
                    mma_bf16(acc[mt][nt], afr[mt], lp);
                }
#pragma unroll
            for (int mt = 0; mt < 2; mt++) {
                uint32_t off = (uint32_t)(((aRowL + mt * 16) * SAS + aColL + kk) * 2);
                ldsm4(afr[mt], sAl_b + off);
            }
#pragma unroll
            for (int mt = 0; mt < 2; mt++)
#pragma unroll
                for (int nt = 0; nt < 4; nt++)
                    mma_bf16(acc[mt][nt], afr[mt], &bh[(nt >> 1) * 4 + (nt & 1) * 2]);
        }

        if (c + 1 < nchunk) {
            __syncthreads();   // all reads of current chunk done
            sts();
            __syncthreads();
        }
    }

    // ---- epilogue ----
    const int r0 = bm + wm * 32 + (lane >> 2);
    const int c0 = bn + wn * 32 + (lane & 3) * 2;
#pragma unroll
    for (int mt = 0; mt < 2; mt++)
#pragma unroll
        for (int nt = 0; nt < 4; nt++) {
            const int row = r0 + mt * 16;
            const int col = c0 + nt * 8;
            float2 v0, v1;
            v0.x = acc[mt][nt][0] * alpha; v0.y = acc[mt][nt][1] * alpha;
            v1.x = acc[mt][nt][2] * alpha; v1.y = acc[mt][nt][3] * alpha;
            if (bias) {
                v0.x += bias[col]; v0.y += bias[col + 1];
                v1.x += bias[col]; v1.y += bias[col + 1];
            }
            *reinterpret_cast<float2*>(C + (size_t)row * ldc + col) = v0;
            *reinterpret_cast<float2*>(C + (size_t)(row + 8) * ldc + col) = v1;
        }
}

// ---------------- K1: projections qp = query@Wq, kp = key@Wk, vp = value@Wq ----------------
__global__ void __launch_bounds__(256) k_proj(
    const float* __restrict__ q, const float* __restrict__ k,
    const float* __restrict__ v,
    const float* __restrict__ Wq, const float* __restrict__ Wk)
{
    int z = blockIdx.z;
    const float* A = (z == 0) ? q : (z == 1) ? k : v;
    const float* W = (z == 1) ? Wk : Wq;   // value uses Wq (bug preserved from source)
    float* C = (z == 0) ? g_qp : (z == 1) ? g_kp : g_vp;
    gemm_mma<false>(A, NE, W, NE, C, NE, NE, 1.0f, nullptr);
}

// ---------------- K2 (merged): wk2 (z<8), S1 (z in 8..23) ----------------
__global__ void __launch_bounds__(256) k_mid(const float* __restrict__ Wr)
{
    const int z = blockIdx.z;
    if (z < 8) {
        // Wk2[b,k,h,:] = (1/8) * kp_head(b,k,h,:) @ Wr[h*64:(h+1)*64, :]
        const int h = z;
        gemm_mma<false>(g_kp + h * ND, NE,
                        Wr + (size_t)h * ND * NE, NE,
                        g_wk2 + (size_t)h * NE, NH * NE,
                        ND, 0.125f, nullptr);
    } else {
        // S1[b,h,q,k] = (1/8) * qp_h @ kp_h^T
        if (blockIdx.x >= 4 || blockIdx.y >= 2) return;
        const int zz = z - 8;            // b*NH + h
        const int b = zz >> 3, h = zz & 7;
        gemm_mma<true>(g_qp + (size_t)b * NL * NE + h * ND, NE,
                       g_kp + (size_t)b * NL * NE + h * ND, NE,
                       g_S1 + (size_t)zz * NL * NL, NL,
                       ND, 0.125f, nullptr);
    }
}

// ---------------- K3: bias2[b,k,h] = (1/8) * dot(br_head, kp_head) ----------------
__global__ void k_bias2(const float* __restrict__ br)
{
    int idx = blockIdx.x * blockDim.x + threadIdx.x;  // NB*NL*NH = 4096
    if (idx >= NB * NL * NH) return;
    int h = idx & (NH - 1);
    int row = idx >> 3;
    float s = 0.f;
#pragma unroll 8
    for (int e = 0; e < ND; e++)
        s += br[h * ND + e] * g_kp[(size_t)row * NE + h * ND + e];
    g_bias2[idx] = s * 0.125f;
}

// ---------------- K4: relation streaming pass (head-paired f32x2) ----------------
// Launch index 3 -> this is the kernel ncu captures.
__global__ void __launch_bounds__(256, 2) k_rel(const float* __restrict__ relation)
{
    const int kpos = blockIdx.x;
    const int b = blockIdx.y;
    const int tid = threadIdx.x;
    const int warp = tid >> 5;
    const int lane = tid & 31;

    // packed wk2: wp[hp][g] = (wk2[2hp][g], wk2[2hp+1][g]), hp = 0..3
    __shared__ unsigned long long wp[NH / 2][NE];   // 16 KB
    __shared__ float b2s[NH];

    {
        const float* src = g_wk2 + (size_t)(b * NL + kpos) * NH * NE;
        for (int i = tid; i < (NH / 2) * NE; i += 256) {
            int hp = i >> 9;          // /512
            int g = i & (NE - 1);
            wp[hp][g] = f2pack(src[(2 * hp) * NE + g], src[(2 * hp + 1) * NE + g]);
        }
        if (tid < NH) b2s[tid] = g_bias2[(size_t)(b * NL + kpos) * NH + tid];
    }
    __syncthreads();

    for (int pass = 0; pass < 8; pass++) {
        const int q0 = pass * 32 + warp * 4;   // this warp: q0..q0+3

        const float4* rp[4];
#pragma unroll
        for (int qq = 0; qq < 4; qq++)
            rp[qq] = reinterpret_cast<const float4*>(
                relation + ((size_t)(b * NL + q0 + qq) * NL + kpos) * NE);

        unsigned long long acc[4][4];   // [qq][hp]
#pragma unroll
        for (int qq = 0; qq < 4; qq++)
#pragma unroll
            for (int hp = 0; hp < 4; hp++) acc[qq][hp] = 0ull;

#pragma unroll
        for (int i128 = 0; i128 < 4; i128++) {
            const int g0 = i128 * 128 + lane * 4;
            // w pairs for this g-window, all 4 head-pairs
            unsigned long long w[4][4];
#pragma unroll
            for (int hp = 0; hp < 4; hp++) {
                ulonglong2 wa = *reinterpret_cast<const ulonglong2*>(&wp[hp][g0]);
                ulonglong2 wb = *reinterpret_cast<const ulonglong2*>(&wp[hp][g0 + 2]);
                w[hp][0] = wa.x; w[hp][1] = wa.y; w[hp][2] = wb.x; w[hp][3] = wb.y;
            }
#pragma unroll
            for (int qq = 0; qq < 4; qq++) {
                float4 r = rp[qq][i128 * 32 + lane];
                unsigned long long rx = f2pack(r.x, r.x);
                unsigned long long ry = f2pack(r.y, r.y);
                unsigned long long rz = f2pack(r.z, r.z);
                unsigned long long rw = f2pack(r.w, r.w);
#pragma unroll
                for (int hp = 0; hp < 4; hp++) {
                    fma2(acc[qq][hp], rx, w[hp][0]);
                    fma2(acc[qq][hp], ry, w[hp][1]);
                    fma2(acc[qq][hp], rz, w[hp][2]);
                    fma2(acc[qq][hp], rw, w[hp][3]);
                }
            }
        }

        // unpack to vals[qq*8 + h] then transpose-reduce
        float vals[32];
#pragma unroll
        for (int qq = 0; qq < 4; qq++)
#pragma unroll
            for (int hp = 0; hp < 4; hp++)
                f2unpack(vals[qq * 8 + 2 * hp], vals[qq * 8 + 2 * hp + 1], acc[qq][hp]);

#pragma unroll
        for (int off = 16; off > 0; off >>= 1) {
            bool hi = (lane & off) != 0;
#pragma unroll
            for (int i = 0; i < 16; i++) {
                if (i < off) {
                    float send = hi ? vals[i] : vals[i + off];
                    float recv = __shfl_xor_sync(0xffffffffu, send, off);
                    vals[i] = (hi ? vals[i + off] : vals[i]) + recv;
                }
            }
        }

        const int qq = lane >> 3;
        const int h = lane & 7;
        const int q = q0 + qq;
        float s1 = g_S1[(((size_t)b * NH + h) * NL + q) * NL + kpos];
        g_S[(((size_t)b * NL + q) * NL + kpos) * NH + h] = vals[0] + s1 + b2s[h];
    }
}

// ---------------- K5: softmax over k + write probs ----------------
__global__ void __launch_bounds__(256) k_softmax(float* __restrict__ a_out, int write_a)
{
    const int q = blockIdx.x;
    const int b = blockIdx.y;
    const int tid = threadIdx.x;
    const int warp = tid >> 5;   // = head
    const int lane = tid & 31;

    __shared__ float Ss[NL][NH + 1];   // padded

    const float* Srow = g_S + (size_t)(b * NL + q) * NL * NH;
    for (int i = tid; i < NL * NH / 4; i += 256) {
        float4 v = reinterpret_cast<const float4*>(Srow)[i];
        int idx = i * 4;
        int kk = idx >> 3, h0 = idx & 7;
        Ss[kk][h0] = v.x; Ss[kk][h0 + 1] = v.y;
        Ss[kk][h0 + 2] = v.z; Ss[kk][h0 + 3] = v.w;
    }
    __syncthreads();

    const int h = warp;
    float x[8];
#pragma unroll
    for (int i = 0; i < 8; i++) x[i] = Ss[lane + 32 * i][h];

    float m = x[0];
#pragma unroll
    for (int i = 1; i < 8; i++) m = fmaxf(m, x[i]);
#pragma unroll
    for (int off = 16; off > 0; off >>= 1)
        m = fmaxf(m, __shfl_xor_sync(0xffffffffu, m, off));

    float e[8], s = 0.f;
#pragma unroll
    for (int i = 0; i < 8; i++) { e[i] = __expf(x[i] - m); s += e[i]; }
#pragma unroll
    for (int off = 16; off > 0; off >>= 1)
        s += __shfl_xor_sync(0xffffffffu, s, off);
    float inv = 1.0f / s;

    float* Prow = g_P + (((size_t)b * NH + h) * NL + q) * NL;
#pragma unroll
    for (int i = 0; i < 8; i++) {
        float p = e[i] * inv;
        Prow[lane + 32 * i] = p;
        Ss[lane + 32 * i][h] = p;    // own column only
    }
    __syncthreads();

    if (write_a) {
        float* arow = a_out + (size_t)(b * NL + q) * NL * NH;
        int t = tid;
        float4 v0 = make_float4(Ss[t][0], Ss[t][1], Ss[t][2], Ss[t][3]);
        float4 v1 = make_float4(Ss[t][4], Ss[t][5], Ss[t][6], Ss[t][7]);
        reinterpret_cast<float4*>(arow + t * 8)[0] = v0;
        reinterpret_cast<float4*>(arow + t * 8)[1] = v1;
    }
}

// ---------------- K6: attn = P @ vp per (b,h) ----------------
__global__ void __launch_bounds__(256) k_attn()
{
    int z = blockIdx.z;           // b*NH + h
    int b = z >> 3, h = z & 7;
    const float* A = g_P + (size_t)z * NL * NL;              // L x L
    const float* Bw = g_vp + (size_t)b * NL * NE + h * ND;   // L x 64, ldb=NE
    float* C = g_attn + (size_t)b * NL * NE + h * ND;        // ldc=NE
    gemm_mma<false>(A, NL, Bw, NE, C, NE, NL, 1.0f, nullptr);
}

// ---------------- K7: out = attn @ Wo^T + bo ----------------
__global__ void __launch_bounds__(256) k_out(
    const float* __restrict__ Wo, const float* __restrict__ bo,
    float* __restrict__ out)
{
    gemm_mma<true>(g_attn, NE, Wo, NE, out, NE, NE, 1.0f, bo);
}

// ---------------- launch ----------------
extern "C" void kernel_launch(void* const* d_in, const int* in_sizes, int n_in,
                              void* d_out, int out_size)
{
    const float* query    = (const float*)d_in[0];
    const float* key      = (const float*)d_in[1];
    const float* value    = (const float*)d_in[2];
    const float* relation = (const float*)d_in[3];
    const float* Wq       = (const float*)d_in[4];
    const float* Wk       = (const float*)d_in[5];
    // d_in[6] = Wv — unused (source bug: value projected with Wq)
    const float* Wr       = (const float*)d_in[7];
    const float* br       = (const float*)d_in[8];
    const float* Wo       = (const float*)d_in[9];
    const float* bo       = (const float*)d_in[10];

    float* out = (float*)d_out;
    const int out_elems = NB * NL * NE;            // 262144
    const int a_elems   = NB * NL * NL * NH;       // 1048576
    int write_a = (out_size >= out_elems + a_elems) ? 1 : 0;
    float* a_out = out + out_elems;

    dim3 blk(256);
    k_proj   <<<dim3(8, 4, 3),   blk>>>(query, key, value, Wq, Wk);
    k_mid    <<<dim3(8, 4, 24),  blk>>>(Wr);
    k_bias2  <<<16, 256>>>(br);
    k_rel    <<<dim3(NL, NB),    blk>>>(relation);   // launch index 3 -> profiled
    k_softmax<<<dim3(NL, NB),    blk>>>(a_out, write_a);
    k_attn   <<<dim3(1, 2, 16),  blk>>>();
    k_out    <<<dim3(8, 4, 1),   blk>>>(Wo, bo, out);
}

// round 11
// speedup vs baseline: 1.8409x; 1.0805x over previous
#include <cuda_runtime.h>
#include <cuda_bf16.h>
#include <cstdint>

// Problem constants
#define NB 2
#define NL 256
#define NE 512
#define NH 8
#define ND 64   // head dim
// scale = 1/sqrt(64) = 0.125

// ---------------- device scratch (no allocations allowed) ----------------
__device__ float g_qp[NB*NL*NE];
__device__ float g_kp[NB*NL*NE];
__device__ float g_vp[NB*NL*NE];
__device__ float g_wk2[NB*NL*NH*NE];     // [b,k,h,g], pre-scaled by 1/8
__device__ float g_bias2[NB*NL*NH];      // pre-scaled by 1/8
__device__ float g_S1[NB*NH*NL*NL];      // [b,h,q,k], pre-scaled by 1/8
__device__ float g_S[NB*NL*NL*NH];       // logits, [b,q,k,h]
__device__ float g_P[NB*NH*NL*NL];       // probs, [b,h,q,k]
__device__ float g_attn[NB*NL*NE];       // [b,q, h*64+e]

// ---------------- packed f32x2 helpers ----------------
__device__ __forceinline__ unsigned long long f2pack(float lo, float hi) {
    unsigned long long r;
    asm("mov.b64 %0, {%1, %2};" : "=l"(r) : "f"(lo), "f"(hi));
    return r;
}
__device__ __forceinline__ void f2unpack(float& lo, float& hi, unsigned long long v) {
    asm("mov.b64 {%0, %1}, %2;" : "=f"(lo), "=f"(hi) : "l"(v));
}
__device__ __forceinline__ void fma2(unsigned long long& d,
                                     unsigned long long a, unsigned long long b) {
    asm("fma.rn.f32x2 %0, %1, %2, %0;" : "+l"(d) : "l"(a), "l"(b));
}

// ---------------- cp.async helpers (base PTX, sm_80+) ----------------
#define CP_ASYNC_CG(dst_u32, src_ptr) \
    asm volatile("cp.async.cg.shared.global [%0], [%1], 16;" \
        :: "r"(dst_u32), "l"(src_ptr) : "memory")
#define CP_ASYNC_COMMIT() \
    asm volatile("cp.async.commit_group;" ::: "memory")
#define CP_ASYNC_WAIT(N) \
    asm volatile("cp.async.wait_group %0;" :: "n"(N) : "memory")

// ---------------- warp-mma helpers (base PTX, sm_80+: valid on sm_103) ----------------
__device__ __forceinline__ uint32_t smem_addr_u32(const void* p) {
    return (uint32_t)__cvta_generic_to_shared(p);
}
__device__ __forceinline__ void ldsm4(uint32_t* r, uint32_t a) {
    asm volatile("ldmatrix.sync.aligned.m8n8.x4.shared.b16 {%0,%1,%2,%3}, [%4];"
        : "=r"(r[0]), "=r"(r[1]), "=r"(r[2]), "=r"(r[3]) : "r"(a));
}
__device__ __forceinline__ void ldsm4t(uint32_t* r, uint32_t a) {
    asm volatile("ldmatrix.sync.aligned.m8n8.x4.trans.shared.b16 {%0,%1,%2,%3}, [%4];"
        : "=r"(r[0]), "=r"(r[1]), "=r"(r[2]), "=r"(r[3]) : "r"(a));
}
__device__ __forceinline__ void mma_bf16(float* c, const uint32_t* a, const uint32_t* b) {
    asm volatile("mma.sync.aligned.m16n8k16.row.col.f32.bf16.bf16.f32 "
        "{%0,%1,%2,%3}, {%4,%5,%6,%7}, {%8,%9}, {%0,%1,%2,%3};"
        : "+f"(c[0]), "+f"(c[1]), "+f"(c[2]), "+f"(c[3])
        : "r"(a[0]), "r"(a[1]), "r"(a[2]), "r"(a[3]), "r"(b[0]), "r"(b[1]));
}

// ---------------- GEMM v5b: bf16-split tensor-core GEMM with LDG prefetch ----------------
// C[m,n] = alpha * sum_k A[m,k]*B[k,n]   (TRANS_B: B stored [n,k])  (+bias[n])
// Block tile 128(m) x 64(n), 256 threads = 8 warps (4m x 2n), warp tile 32x32.
template<bool TRANS_B>
__device__ __forceinline__ void gemm_mma(
    const float* __restrict__ A, int lda,
    const float* __restrict__ B, int ldb,
    float* __restrict__ C, int ldc,
    int K, float alpha, const float* __restrict__ bias)
{
    constexpr int SAS = 40;                  // sA row stride (elems): 80B, 16B-aligned
    constexpr int SBR = TRANS_B ? 64 : 32;   // sB rows
    constexpr int SBS = TRANS_B ? 40 : 72;   // sB row stride (80B / 144B)
    __shared__ __nv_bfloat16 sAh[128 * SAS], sAl[128 * SAS];
    __shared__ __nv_bfloat16 sBh[SBR * SBS], sBl[SBR * SBS];

    const int tid = threadIdx.x;
    const int lane = tid & 31;
    const int wid = tid >> 5;
    const int wm = wid & 3;                  // warp m index (0..3)
    const int wn = wid >> 2;                 // warp n index (0..1)
    const int bm = blockIdx.y * 128;
    const int bn = blockIdx.x * 64;

    const uint32_t sAh_b = smem_addr_u32(sAh);
    const uint32_t sAl_b = smem_addr_u32(sAl);
    const uint32_t sBh_b = smem_addr_u32(sBh);
    const uint32_t sBl_b = smem_addr_u32(sBl);

    const int aRowL = wm * 32 + (lane & 15);          // + mt*16
    const int aColL = (lane >> 4) * 8;                // + kk
    const int bRowL = TRANS_B ? (wn * 32 + (lane & 7) + (lane >> 4) * 8)
                              : ((lane & 7) + ((lane >> 3) & 1) * 8);
    const int bColL = TRANS_B ? (((lane >> 3) & 1) * 8)
                              : (wn * 32 + (lane >> 4) * 8);

    // staging indices
    const int aSRow = tid >> 3, aSC4 = (tid & 7) * 4;
    const int bSRowN = tid >> 4, bSC4N = (tid & 15) * 4;
    const int bSRowT = tid >> 3, bSC4T = (tid & 7) * 4;

    float4 aR[4], bR[2];
    auto ldg = [&](int k0) {
#pragma unroll
        for (int i = 0; i < 4; i++)
            aR[i] = *reinterpret_cast<const float4*>(
                A + (size_t)(bm + aSRow + i * 32) * lda + k0 + aSC4);
#pragma unroll
        for (int i = 0; i < 2; i++) {
            if (!TRANS_B)
                bR[i] = *reinterpret_cast<const float4*>(
                    B + (size_t)(k0 + bSRowN + i * 16) * ldb + bn + bSC4N);
            else
                bR[i] = *reinterpret_cast<const float4*>(
                    B + (size_t)(bn + bSRowT + i * 32) * ldb + k0 + bSC4T);
        }
    };
    auto split_store = [&](__nv_bfloat16* hB, __nv_bfloat16* lB, int idx, float4 v) {
        __nv_bfloat162 h01 = __floats2bfloat162_rn(v.x, v.y);
        __nv_bfloat162 h23 = __floats2bfloat162_rn(v.z, v.w);
        float2 f01 = __bfloat1622float2(h01);
        float2 f23 = __bfloat1622float2(h23);
        __nv_bfloat162 l01 = __floats2bfloat162_rn(v.x - f01.x, v.y - f01.y);
        __nv_bfloat162 l23 = __floats2bfloat162_rn(v.z - f23.x, v.w - f23.y);
        *reinterpret_cast<__nv_bfloat162*>(&hB[idx])     = h01;
        *reinterpret_cast<__nv_bfloat162*>(&hB[idx + 2]) = h23;
        *reinterpret_cast<__nv_bfloat162*>(&lB[idx])     = l01;
        *reinterpret_cast<__nv_bfloat162*>(&lB[idx + 2]) = l23;
    };
    auto sts = [&]() {
#pragma unroll
        for (int i = 0; i < 4; i++)
            split_store(sAh, sAl, (aSRow + i * 32) * SAS + aSC4, aR[i]);
#pragma unroll
        for (int i = 0; i < 2; i++) {
            int idx = (!TRANS_B) ? ((bSRowN + i * 16) * SBS + bSC4N)
                                 : ((bSRowT + i * 32) * SBS + bSC4T);
            split_store(sBh, sBl, idx, bR[i]);
        }
    };

    float acc[2][4][4];
#pragma unroll
    for (int mt = 0; mt < 2; mt++)
#pragma unroll
        for (int nt = 0; nt < 4; nt++)
#pragma unroll
            for (int j = 0; j < 4; j++) acc[mt][nt][j] = 0.f;

    const int nchunk = K / 32;
    ldg(0);
    sts();
    __syncthreads();

    for (int c = 0; c < nchunk; ++c) {
        if (c + 1 < nchunk) ldg((c + 1) * 32);   // prefetch overlaps MMAs below

#pragma unroll
        for (int kk = 0; kk < 32; kk += 16) {
            uint32_t afr[2][4], bh[8], bl[8];
#pragma unroll
            for (int mt = 0; mt < 2; mt++) {
                uint32_t off = (uint32_t)(((aRowL + mt * 16) * SAS + aColL + kk) * 2);
                ldsm4(afr[mt], sAh_b + off);
            }
#pragma unroll
            for (int ntp = 0; ntp < 2; ntp++) {
                uint32_t off;
                if (!TRANS_B)
                    off = (uint32_t)(((bRowL + kk) * SBS + bColL + ntp * 16) * 2);
                else
                    off = (uint32_t)(((bRowL + ntp * 16) * SBS + bColL + kk) * 2);
                if (!TRANS_B) {
                    ldsm4t(&bh[ntp * 4], sBh_b + off);
                    ldsm4t(&bl[ntp * 4], sBl_b + off);
                } else {
                    ldsm4(&bh[ntp * 4], sBh_b + off);
                    ldsm4(&bl[ntp * 4], sBl_b + off);
                }
            }
#pragma unroll
            for (int mt = 0; mt < 2; mt++)
#pragma unroll
                for (int nt = 0; nt < 4; nt++) {
                    const uint32_t* bp = &bh[(nt >> 1) * 4 + (nt & 1) * 2];
                    const uint32_t* lp = &bl[(nt >> 1) * 4 + (nt & 1) * 2];
                    mma_bf16(acc[mt][nt], afr[mt], bp);
                    mma_bf16(acc[mt][nt], afr[mt], lp);
                }
#pragma unroll
            for (int mt = 0; mt < 2; mt++) {
                uint32_t off = (uint32_t)(((aRowL + mt * 16) * SAS + aColL + kk) * 2);
                ldsm4(afr[mt], sAl_b + off);
            }
#pragma unroll
            for (int mt = 0; mt < 2; mt++)
#pragma unroll
                for (int nt = 0; nt < 4; nt++)
                    mma_bf16(acc[mt][nt], afr[mt], &bh[(nt >> 1) * 4 + (nt & 1) * 2]);
        }

        if (c + 1 < nchunk) {
            __syncthreads();
            sts();
            __syncthreads();
        }
    }

    // ---- epilogue ----
    const int r0 = bm + wm * 32 + (lane >> 2);
    const int c0 = bn + wn * 32 + (lane & 3) * 2;
#pragma unroll
    for (int mt = 0; mt < 2; mt++)
#pragma unroll
        for (int nt = 0; nt < 4; nt++) {
            const int row = r0 + mt * 16;
            const int col = c0 + nt * 8;
            float2 v0, v1;
            v0.x = acc[mt][nt][0] * alpha; v0.y = acc[mt][nt][1] * alpha;
            v1.x = acc[mt][nt][2] * alpha; v1.y = acc[mt][nt][3] * alpha;
            if (bias) {
                v0.x += bias[col]; v0.y += bias[col + 1];
                v1.x += bias[col]; v1.y += bias[col + 1];
            }
            *reinterpret_cast<float2*>(C + (size_t)row * ldc + col) = v0;
            *reinterpret_cast<float2*>(C + (size_t)(row + 8) * ldc + col) = v1;
        }
}

// ---------------- K1: projections qp = query@Wq, kp = key@Wk, vp = value@Wq ----------------
__global__ void __launch_bounds__(256) k_proj(
    const float* __restrict__ q, const float* __restrict__ k,
    const float* __restrict__ v,
    const float* __restrict__ Wq, const float* __restrict__ Wk)
{
    int z = blockIdx.z;
    const float* A = (z == 0) ? q : (z == 1) ? k : v;
    const float* W = (z == 1) ? Wk : Wq;   // value uses Wq (bug preserved from source)
    float* C = (z == 0) ? g_qp : (z == 1) ? g_kp : g_vp;
    gemm_mma<false>(A, NE, W, NE, C, NE, NE, 1.0f, nullptr);
}

// ---------------- K2 (merged): wk2 (z<8), S1 (z in 8..23) ----------------
__global__ void __launch_bounds__(256) k_mid(const float* __restrict__ Wr)
{
    const int z = blockIdx.z;
    if (z < 8) {
        // Wk2[b,k,h,:] = (1/8) * kp_head(b,k,h,:) @ Wr[h*64:(h+1)*64, :]
        const int h = z;
        gemm_mma<false>(g_kp + h * ND, NE,
                        Wr + (size_t)h * ND * NE, NE,
                        g_wk2 + (size_t)h * NE, NH * NE,
                        ND, 0.125f, nullptr);
    } else {
        // S1[b,h,q,k] = (1/8) * qp_h @ kp_h^T
        if (blockIdx.x >= 4 || blockIdx.y >= 2) return;
        const int zz = z - 8;            // b*NH + h
        const int b = zz >> 3, h = zz & 7;
        gemm_mma<true>(g_qp + (size_t)b * NL * NE + h * ND, NE,
                       g_kp + (size_t)b * NL * NE + h * ND, NE,
                       g_S1 + (size_t)zz * NL * NL, NL,
                       ND, 0.125f, nullptr);
    }
}

// ---------------- K3: bias2[b,k,h] = (1/8) * dot(br_head, kp_head) ----------------
__global__ void k_bias2(const float* __restrict__ br)
{
    int idx = blockIdx.x * blockDim.x + threadIdx.x;  // NB*NL*NH = 4096
    if (idx >= NB * NL * NH) return;
    int h = idx & (NH - 1);
    int row = idx >> 3;
    float s = 0.f;
#pragma unroll 8
    for (int e = 0; e < ND; e++)
        s += br[h * ND + e] * g_kp[(size_t)row * NE + h * ND + e];
    g_bias2[idx] = s * 0.125f;
}

// ---------------- K4: relation stream, cp.async stage pipeline ----------------
// Block = (kpos, b, qhalf): 128 q-rows, 4 stages x 32 rows x 2KB, 2-slot ring.
// Dynamic smem: wk2 packed 16KB @0, bias2 @16384, ring 2x64KB @16512.
#define REL_SMEM (16512 + 2 * 32 * 512 * 4)
__global__ void __launch_bounds__(256) k_rel(const float* __restrict__ relation)
{
    extern __shared__ char dsm[];
    unsigned long long* wp = reinterpret_cast<unsigned long long*>(dsm);  // [4][512]
    float* b2s = reinterpret_cast<float*>(dsm + 16384);                   // [8]
    float* ring = reinterpret_cast<float*>(dsm + 16512);                  // [2][32][512]

    const int kpos = blockIdx.x;
    const int b = blockIdx.y;
    const int qbase = blockIdx.z * 128;
    const int tid = threadIdx.x;
    const int warp = tid >> 5;
    const int lane = tid & 31;

    const float* relbase = relation + ((size_t)(b * NL + qbase) * NL + kpos) * NE;
    const uint32_t ring_b = smem_addr_u32(ring);

    auto issue_stage = [&](int slot, int sidx) {
        const float* base = relbase + (size_t)sidx * 32 * NL * NE;
        const uint32_t dst0 = ring_b + slot * (32 * 512 * 4);
#pragma unroll
        for (int i = 0; i < 16; i++) {
            int c = tid + i * 256;            // 0..4095 chunk of 16B
            int r = c >> 7;                   // row in stage (128 chunks/row)
            int off = (c & 127) * 4;          // float offset in row
            CP_ASYNC_CG(dst0 + (uint32_t)c * 16, base + (size_t)r * (NL * NE) + off);
        }
        CP_ASYNC_COMMIT();
    };

    // prologue: get two stages in flight before touching anything else
    issue_stage(0, 0);
    issue_stage(1, 1);

    // load packed wk2 + bias2 (overlaps with cp.async fetch)
    {
        const float* src = g_wk2 + (size_t)(b * NL + kpos) * NH * NE;
        for (int i = tid; i < (NH / 2) * NE; i += 256) {
            int hp = i >> 9;
            int g = i & (NE - 1);
            wp[hp * NE + g] = f2pack(src[(2 * hp) * NE + g], src[(2 * hp + 1) * NE + g]);
        }
        if (tid < NH) b2s[tid] = g_bias2[(size_t)(b * NL + kpos) * NH + tid];
    }

    for (int s = 0; s < 4; ++s) {
        if (s == 3) { CP_ASYNC_WAIT(0); } else { CP_ASYNC_WAIT(1); }
        __syncthreads();   // stage s visible to all; also fences wk2 on s==0

        const int slot = s & 1;
        const float* stf = ring + slot * (32 * 512);

        unsigned long long acc[4][4];   // [qq][hp]
#pragma unroll
        for (int qq = 0; qq < 4; qq++)
#pragma unroll
            for (int hp = 0; hp < 4; hp++) acc[qq][hp] = 0ull;

#pragma unroll
        for (int i128 = 0; i128 < 4; i128++) {
            const int g0 = i128 * 128 + lane * 4;
            unsigned long long w[4][4];
#pragma unroll
            for (int hp = 0; hp < 4; hp++) {
                ulonglong2 wa = *reinterpret_cast<const ulonglong2*>(&wp[hp * NE + g0]);
                ulonglong2 wb = *reinterpret_cast<const ulonglong2*>(&wp[hp * NE + g0 + 2]);
                w[hp][0] = wa.x; w[hp][1] = wa.y; w[hp][2] = wb.x; w[hp][3] = wb.y;
            }
#pragma unroll
            for (int qq = 0; qq < 4; qq++) {
                float4 r = *reinterpret_cast<const float4*>(
                    stf + (warp * 4 + qq) * 512 + g0);
                unsigned long long rx = f2pack(r.x, r.x);
                unsigned long long ry = f2pack(r.y, r.y);
                unsigned long long rz = f2pack(r.z, r.z);
                unsigned long long rw = f2pack(r.w, r.w);
#pragma unroll
                for (int hp = 0; hp < 4; hp++) {
                    fma2(acc[qq][hp], rx, w[hp][0]);
                    fma2(acc[qq][hp], ry, w[hp][1]);
                    fma2(acc[qq][hp], rz, w[hp][2]);
                    fma2(acc[qq][hp], rw, w[hp][3]);
                }
            }
        }

        // unpack to vals[qq*8 + h] then transpose-reduce
        float vals[32];
#pragma unroll
        for (int qq = 0; qq < 4; qq++)
#pragma unroll
            for (int hp = 0; hp < 4; hp++)
                f2unpack(vals[qq * 8 + 2 * hp], vals[qq * 8 + 2 * hp + 1], acc[qq][hp]);

#pragma unroll
        for (int off = 16; off > 0; off >>= 1) {
            bool hi = (lane & off) != 0;
#pragma unroll
            for (int i = 0; i < 16; i++) {
                if (i < off) {
                    float send = hi ? vals[i] : vals[i + off];
                    float recv = __shfl_xor_sync(0xffffffffu, send, off);
                    vals[i] = (hi ? vals[i + off] : vals[i]) + recv;
                }
            }
        }

        {
            const int qq = lane >> 3;
            const int h = lane & 7;
            const int q = qbase + s * 32 + warp * 4 + qq;
            float s1 = g_S1[(((size_t)b * NH + h) * NL + q) * NL + kpos];
            g_S[(((size_t)b * NL + q) * NL + kpos) * NH + h] = vals[0] + s1 + b2s[h];
        }

        __syncthreads();   // all reads of slot done before refill
        if (s + 2 < 4) issue_stage(slot, s + 2);
    }
}

// ---------------- K5: softmax over k + write probs ----------------
__global__ void __launch_bounds__(256) k_softmax(float* __restrict__ a_out, int write_a)
{
    const int q = blockIdx.x;
    const int b = blockIdx.y;
    const int tid = threadIdx.x;
    const int warp = tid >> 5;   // = head
    const int lane = tid & 31;

    __shared__ float Ss[NL][NH + 1];   // padded

    const float* Srow = g_S + (size_t)(b * NL + q) * NL * NH;
    for (int i = tid; i < NL * NH / 4; i += 256) {
        float4 v = reinterpret_cast<const float4*>(Srow)[i];
        int idx = i * 4;
        int kk = idx >> 3, h0 = idx & 7;
        Ss[kk][h0] = v.x; Ss[kk][h0 + 1] = v.y;
        Ss[kk][h0 + 2] = v.z; Ss[kk][h0 + 3] = v.w;
    }
    __syncthreads();

    const int h = warp;
    float x[8];
#pragma unroll
    for (int i = 0; i < 8; i++) x[i] = Ss[lane + 32 * i][h];

    float m = x[0];
#pragma unroll
    for (int i = 1; i < 8; i++) m = fmaxf(m, x[i]);
#pragma unroll
    for (int off = 16; off > 0; off >>= 1)
        m = fmaxf(m, __shfl_xor_sync(0xffffffffu, m, off));

    float e[8], s = 0.f;
#pragma unroll
    for (int i = 0; i < 8; i++) { e[i] = __expf(x[i] - m); s += e[i]; }
#pragma unroll
    for (int off = 16; off > 0; off >>= 1)
        s += __shfl_xor_sync(0xffffffffu, s, off);
    float inv = 1.0f / s;

    float* Prow = g_P + (((size_t)b * NH + h) * NL + q) * NL;
#pragma unroll
    for (int i = 0; i < 8; i++) {
        float p = e[i] * inv;
        Prow[lane + 32 * i] = p;
        Ss[lane + 32 * i][h] = p;    // own column only
    }
    __syncthreads();

    if (write_a) {
        float* arow = a_out + (size_t)(b * NL + q) * NL * NH;
        int t = tid;
        float4 v0 = make_float4(Ss[t][0], Ss[t][1], Ss[t][2], Ss[t][3]);
        float4 v1 = make_float4(Ss[t][4], Ss[t][5], Ss[t][6], Ss[t][7]);
        reinterpret_cast<float4*>(arow + t * 8)[0] = v0;
        reinterpret_cast<float4*>(arow + t * 8)[1] = v1;
    }
}

// ---------------- K6: attn = P @ vp per (b,h) ----------------
__global__ void __launch_bounds__(256) k_attn()
{
    int z = blockIdx.z;           // b*NH + h
    int b = z >> 3, h = z & 7;
    const float* A = g_P + (size_t)z * NL * NL;              // L x L
    const float* Bw = g_vp + (size_t)b * NL * NE + h * ND;   // L x 64, ldb=NE
    float* C = g_attn + (size_t)b * NL * NE + h * ND;        // ldc=NE
    gemm_mma<false>(A, NL, Bw, NE, C, NE, NL, 1.0f, nullptr);
}

// ---------------- K7: out = attn @ Wo^T + bo ----------------
__global__ void __launch_bounds__(256) k_out(
    const float* __restrict__ Wo, const float* __restrict__ bo,
    float* __restrict__ out)
{
    gemm_mma<true>(g_attn, NE, Wo, NE, out, NE, NE, 1.0f, bo);
}

// ---------------- launch ----------------
extern "C" void kernel_launch(void* const* d_in, const int* in_sizes, int n_in,
                              void* d_out, int out_size)
{
    const float* query    = (const float*)d_in[0];
    const float* key      = (const float*)d_in[1];
    const float* value    = (const float*)d_in[2];
    const float* relation = (const float*)d_in[3];
    const float* Wq       = (const float*)d_in[4];
    const float* Wk       = (const float*)d_in[5];
    // d_in[6] = Wv — unused (source bug: value projected with Wq)
    const float* Wr       = (const float*)d_in[7];
    const float* br       = (const float*)d_in[8];
    const float* Wo       = (const float*)d_in[9];
    const float* bo       = (const float*)d_in[10];

    float* out = (float*)d_out;
    const int out_elems = NB * NL * NE;            // 262144
    const int a_elems   = NB * NL * NL * NH;       // 1048576
    int write_a = (out_size >= out_elems + a_elems) ? 1 : 0;
    float* a_out = out + out_elems;

    // raise dynamic-smem limit for k_rel (capture-safe: not a stream op)
    cudaFuncSetAttribute((const void*)k_rel,
                         cudaFuncAttributeMaxDynamicSharedMemorySize, REL_SMEM);

    dim3 blk(256);
    k_proj   <<<dim3(8, 4, 3),   blk>>>(query, key, value, Wq, Wk);
    k_mid    <<<dim3(8, 4, 24),  blk>>>(Wr);
    k_bias2  <<<16, 256>>>(br);
    k_rel    <<<dim3(NL, NB, 2), blk, REL_SMEM>>>(relation);   // index 3 -> profiled
    k_softmax<<<dim3(NL, NB),    blk>>>(a_out, write_a);
    k_attn   <<<dim3(1, 2, 16),  blk>>>();
    k_out    <<<dim3(8, 4, 1),   blk>>>(Wo, bo, out);
}

// round 12
// speedup vs baseline: 1.9073x; 1.0361x over previous
#include <cuda_runtime.h>
#include <cuda_bf16.h>
#include <cstdint>

// Problem constants
#define NB 2
#define NL 256
#define NE 512
#define NH 8
#define ND 64   // head dim
// scale = 1/sqrt(64) = 0.125

// ---------------- device scratch (no allocations allowed) ----------------
__device__ float g_qp[NB*NL*NE];
__device__ float g_kp[NB*NL*NE];
__device__ float g_vp[NB*NL*NE];
__device__ float g_wk2[NB*NL*NH*NE];     // [b,k,h,g], pre-scaled by 1/8
__device__ float g_bias2[NB*NL*NH];      // pre-scaled by 1/8
__device__ float g_S1[NB*NH*NL*NL];      // [b,h,q,k], pre-scaled by 1/8
__device__ float g_S[NB*NL*NL*NH];       // logits, [b,q,k,h]
__device__ float g_P[NB*NH*NL*NL];       // probs, [b,h,q,k]
__device__ float g_attn[NB*NL*NE];       // [b,q, h*64+e]

// ---------------- packed f32x2 helpers ----------------
__device__ __forceinline__ unsigned long long f2pack(float lo, float hi) {
    unsigned long long r;
    asm("mov.b64 %0, {%1, %2};" : "=l"(r) : "f"(lo), "f"(hi));
    return r;
}
__device__ __forceinline__ void f2unpack(float& lo, float& hi, unsigned long long v) {
    asm("mov.b64 {%0, %1}, %2;" : "=f"(lo), "=f"(hi) : "l"(v));
}
__device__ __forceinline__ void fma2(unsigned long long& d,
                                     unsigned long long a, unsigned long long b) {
    asm("fma.rn.f32x2 %0, %1, %2, %0;" : "+l"(d) : "l"(a), "l"(b));
}

// ---------------- cp.async helpers (base PTX, sm_80+) ----------------
#define CP_ASYNC_CG(dst_u32, src_ptr) \
    asm volatile("cp.async.cg.shared.global [%0], [%1], 16;" \
        :: "r"(dst_u32), "l"(src_ptr) : "memory")
#define CP_ASYNC_COMMIT() \
    asm volatile("cp.async.commit_group;" ::: "memory")
#define CP_ASYNC_WAIT(N) \
    asm volatile("cp.async.wait_group %0;" :: "n"(N) : "memory")

// ---------------- warp-mma helpers (base PTX, sm_80+: valid on sm_103) ----------------
__device__ __forceinline__ uint32_t smem_addr_u32(const void* p) {
    return (uint32_t)__cvta_generic_to_shared(p);
}
__device__ __forceinline__ void ldsm4(uint32_t* r, uint32_t a) {
    asm volatile("ldmatrix.sync.aligned.m8n8.x4.shared.b16 {%0,%1,%2,%3}, [%4];"
        : "=r"(r[0]), "=r"(r[1]), "=r"(r[2]), "=r"(r[3]) : "r"(a));
}
__device__ __forceinline__ void ldsm4t(uint32_t* r, uint32_t a) {
    asm volatile("ldmatrix.sync.aligned.m8n8.x4.trans.shared.b16 {%0,%1,%2,%3}, [%4];"
        : "=r"(r[0]), "=r"(r[1]), "=r"(r[2]), "=r"(r[3]) : "r"(a));
}
__device__ __forceinline__ void mma_bf16(float* c, const uint32_t* a, const uint32_t* b) {
    asm volatile("mma.sync.aligned.m16n8k16.row.col.f32.bf16.bf16.f32 "
        "{%0,%1,%2,%3}, {%4,%5,%6,%7}, {%8,%9}, {%0,%1,%2,%3};"
        : "+f"(c[0]), "+f"(c[1]), "+f"(c[2]), "+f"(c[3])
        : "r"(a[0]), "r"(a[1]), "r"(a[2]), "r"(a[3]), "r"(b[0]), "r"(b[1]));
}

// ---------------- GEMM v5b: bf16-split tensor-core GEMM with LDG prefetch ----------------
// C[m,n] = alpha * sum_k A[m,k]*B[k,n]   (TRANS_B: B stored [n,k])  (+bias[n])
// Block tile 128(m) x 64(n), 256 threads = 8 warps (4m x 2n), warp tile 32x32.
template<bool TRANS_B>
__device__ __forceinline__ void gemm_mma(
    const float* __restrict__ A, int lda,
    const float* __restrict__ B, int ldb,
    float* __restrict__ C, int ldc,
    int K, float alpha, const float* __restrict__ bias)
{
    constexpr int SAS = 40;                  // sA row stride (elems): 80B, 16B-aligned
    constexpr int SBR = TRANS_B ? 64 : 32;   // sB rows
    constexpr int SBS = TRANS_B ? 40 : 72;   // sB row stride (80B / 144B)
    __shared__ __nv_bfloat16 sAh[128 * SAS], sAl[128 * SAS];
    __shared__ __nv_bfloat16 sBh[SBR * SBS], sBl[SBR * SBS];

    const int tid = threadIdx.x;
    const int lane = tid & 31;
    const int wid = tid >> 5;
    const int wm = wid & 3;                  // warp m index (0..3)
    const int wn = wid >> 2;                 // warp n index (0..1)
    const int bm = blockIdx.y * 128;
    const int bn = blockIdx.x * 64;

    const uint32_t sAh_b = smem_addr_u32(sAh);
    const uint32_t sAl_b = smem_addr_u32(sAl);
    const uint32_t sBh_b = smem_addr_u32(sBh);
    const uint32_t sBl_b = smem_addr_u32(sBl);

    const int aRowL = wm * 32 + (lane & 15);          // + mt*16
    const int aColL = (lane >> 4) * 8;                // + kk
    const int bRowL = TRANS_B ? (wn * 32 + (lane & 7) + (lane >> 4) * 8)
                              : ((lane & 7) + ((lane >> 3) & 1) * 8);
    const int bColL = TRANS_B ? (((lane >> 3) & 1) * 8)
                              : (wn * 32 + (lane >> 4) * 8);

    // staging indices
    const int aSRow = tid >> 3, aSC4 = (tid & 7) * 4;
    const int bSRowN = tid >> 4, bSC4N = (tid & 15) * 4;
    const int bSRowT = tid >> 3, bSC4T = (tid & 7) * 4;

    float4 aR[4], bR[2];
    auto ldg = [&](int k0) {
#pragma unroll
        for (int i = 0; i < 4; i++)
            aR[i] = *reinterpret_cast<const float4*>(
                A + (size_t)(bm + aSRow + i * 32) * lda + k0 + aSC4);
#pragma unroll
        for (int i = 0; i < 2; i++) {
            if (!TRANS_B)
                bR[i] = *reinterpret_cast<const float4*>(
                    B + (size_t)(k0 + bSRowN + i * 16) * ldb + bn + bSC4N);
            else
                bR[i] = *reinterpret_cast<const float4*>(
                    B + (size_t)(bn + bSRowT + i * 32) * ldb + k0 + bSC4T);
        }
    };
    auto split_store = [&](__nv_bfloat16* hB, __nv_bfloat16* lB, int idx, float4 v) {
        __nv_bfloat162 h01 = __floats2bfloat162_rn(v.x, v.y);
        __nv_bfloat162 h23 = __floats2bfloat162_rn(v.z, v.w);
        float2 f01 = __bfloat1622float2(h01);
        float2 f23 = __bfloat1622float2(h23);
        __nv_bfloat162 l01 = __floats2bfloat162_rn(v.x - f01.x, v.y - f01.y);
        __nv_bfloat162 l23 = __floats2bfloat162_rn(v.z - f23.x, v.w - f23.y);
        *reinterpret_cast<__nv_bfloat162*>(&hB[idx])     = h01;
        *reinterpret_cast<__nv_bfloat162*>(&hB[idx + 2]) = h23;
        *reinterpret_cast<__nv_bfloat162*>(&lB[idx])     = l01;
        *reinterpret_cast<__nv_bfloat162*>(&lB[idx + 2]) = l23;
    };
    auto sts = [&]() {
#pragma unroll
        for (int i = 0; i < 4; i++)
            split_store(sAh, sAl, (aSRow + i * 32) * SAS + aSC4, aR[i]);
#pragma unroll
        for (int i = 0; i < 2; i++) {
            int idx = (!TRANS_B) ? ((bSRowN + i * 16) * SBS + bSC4N)
                                 : ((bSRowT + i * 32) * SBS + bSC4T);
            split_store(sBh, sBl, idx, bR[i]);
        }
    };

    float acc[2][4][4];
#pragma unroll
    for (int mt = 0; mt < 2; mt++)
#pragma unroll
        for (int nt = 0; nt < 4; nt++)
#pragma unroll
            for (int j = 0; j < 4; j++) acc[mt][nt][j] = 0.f;

    const int nchunk = K / 32;
    ldg(0);
    sts();
    __syncthreads();

    for (int c = 0; c < nchunk; ++c) {
        if (c + 1 < nchunk) ldg((c + 1) * 32);   // prefetch overlaps MMAs below

#pragma unroll
        for (int kk = 0; kk < 32; kk += 16) {
            uint32_t afr[2][4], bh[8], bl[8];
#pragma unroll
            for (int mt = 0; mt < 2; mt++) {
                uint32_t off = (uint32_t)(((aRowL + mt * 16) * SAS + aColL + kk) * 2);
                ldsm4(afr[mt], sAh_b + off);
            }
#pragma unroll
            for (int ntp = 0; ntp < 2; ntp++) {
                uint32_t off;
                if (!TRANS_B)
                    off = (uint32_t)(((bRowL + kk) * SBS + bColL + ntp * 16) * 2);
                else
                    off = (uint32_t)(((bRowL + ntp * 16) * SBS + bColL + kk) * 2);
                if (!TRANS_B) {
                    ldsm4t(&bh[ntp * 4], sBh_b + off);
                    ldsm4t(&bl[ntp * 4], sBl_b + off);
                } else {
                    ldsm4(&bh[ntp * 4], sBh_b + off);
                    ldsm4(&bl[ntp * 4], sBl_b + off);
                }
            }
#pragma unroll
            for (int mt = 0; mt < 2; mt++)
#pragma unroll
                for (int nt = 0; nt < 4; nt++) {
                    const uint32_t* bp = &bh[(nt >> 1) * 4 + (nt & 1) * 2];
                    const uint32_t* lp = &bl[(nt >> 1) * 4 + (nt & 1) * 2];
                    mma_bf16(acc[mt][nt], afr[mt], bp);
                    mma_bf16(acc[mt][nt], afr[mt], lp);
                }
#pragma unroll
            for (int mt = 0; mt < 2; mt++) {
                uint32_t off = (uint32_t)(((aRowL + mt * 16) * SAS + aColL + kk) * 2);
                ldsm4(afr[mt], sAl_b + off);
            }
#pragma unroll
            for (int mt = 0; mt < 2; mt++)
#pragma unroll
                for (int nt = 0; nt < 4; nt++)
                    mma_bf16(acc[mt][nt], afr[mt], &bh[(nt >> 1) * 4 + (nt & 1) * 2]);
        }

        if (c + 1 < nchunk) {
            __syncthreads();
            sts();
            __syncthreads();
        }
    }

    // ---- epilogue ----
    const int r0 = bm + wm * 32 + (lane >> 2);
    const int c0 = bn + wn * 32 + (lane & 3) * 2;
#pragma unroll
    for (int mt = 0; mt < 2; mt++)
#pragma unroll
        for (int nt = 0; nt < 4; nt++) {
            const int row = r0 + mt * 16;
            const int col = c0 + nt * 8;
            float2 v0, v1;
            v0.x = acc[mt][nt][0] * alpha; v0.y = acc[mt][nt][1] * alpha;
            v1.x = acc[mt][nt][2] * alpha; v1.y = acc[mt][nt][3] * alpha;
            if (bias) {
                v0.x += bias[col]; v0.y += bias[col + 1];
                v1.x += bias[col]; v1.y += bias[col + 1];
            }
            *reinterpret_cast<float2*>(C + (size_t)row * ldc + col) = v0;
            *reinterpret_cast<float2*>(C + (size_t)(row + 8) * ldc + col) = v1;
        }
}

// ---------------- K1: projections qp = query@Wq, kp = key@Wk, vp = value@Wq ----------------
__global__ void __launch_bounds__(256) k_proj(
    const float* __restrict__ q, const float* __restrict__ k,
    const float* __restrict__ v,
    const float* __restrict__ Wq, const float* __restrict__ Wk)
{
    int z = blockIdx.z;
    const float* A = (z == 0) ? q : (z == 1) ? k : v;
    const float* W = (z == 1) ? Wk : Wq;   // value uses Wq (bug preserved from source)
    float* C = (z == 0) ? g_qp : (z == 1) ? g_kp : g_vp;
    gemm_mma<false>(A, NE, W, NE, C, NE, NE, 1.0f, nullptr);
}

// ---------------- K2 (merged): wk2 (z<8), S1 (z in 8..23) ----------------
__global__ void __launch_bounds__(256) k_mid(const float* __restrict__ Wr)
{
    const int z = blockIdx.z;
    if (z < 8) {
        // Wk2[b,k,h,:] = (1/8) * kp_head(b,k,h,:) @ Wr[h*64:(h+1)*64, :]
        const int h = z;
        gemm_mma<false>(g_kp + h * ND, NE,
                        Wr + (size_t)h * ND * NE, NE,
                        g_wk2 + (size_t)h * NE, NH * NE,
                        ND, 0.125f, nullptr);
    } else {
        // S1[b,h,q,k] = (1/8) * qp_h @ kp_h^T
        if (blockIdx.x >= 4 || blockIdx.y >= 2) return;
        const int zz = z - 8;            // b*NH + h
        const int b = zz >> 3, h = zz & 7;
        gemm_mma<true>(g_qp + (size_t)b * NL * NE + h * ND, NE,
                       g_kp + (size_t)b * NL * NE + h * ND, NE,
                       g_S1 + (size_t)zz * NL * NL, NL,
                       ND, 0.125f, nullptr);
    }
}

// ---------------- K3: bias2[b,k,h] = (1/8) * dot(br_head, kp_head) ----------------
__global__ void k_bias2(const float* __restrict__ br)
{
    int idx = blockIdx.x * blockDim.x + threadIdx.x;  // NB*NL*NH = 4096
    if (idx >= NB * NL * NH) return;
    int h = idx & (NH - 1);
    int row = idx >> 3;
    float s = 0.f;
#pragma unroll 8
    for (int e = 0; e < ND; e++)
        s += br[h * ND + e] * g_kp[(size_t)row * NE + h * ND + e];
    g_bias2[idx] = s * 0.125f;
}

// ---------------- K4: relation stream v2 ----------------
// 512 threads (16 warps), block = (kpos, b, qhalf) covering 128 q-rows.
// 4 stages x 32 rows x 2KB in a 3-slot cp.async ring (64KB/slot).
// Warp w handles rows {2w, 2w+1}; g-pair packed f32x2 accumulators, r and wk2
// consumed as native ulonglong2 (zero pack MOVs in the hot loop).
// smem: wk2 raw 16KB @0, bias2 @16384, ring @16512 (3 x 65536) = 213120 B.
#define REL_NSLOT 3
#define REL_STAGE_BYTES (32 * 512 * 4)
#define REL_SMEM (16512 + REL_NSLOT * REL_STAGE_BYTES)
__global__ void __launch_bounds__(512) k_rel(const float* __restrict__ relation)
{
    extern __shared__ char dsm[];
    float* wk  = reinterpret_cast<float*>(dsm);           // [8][512] raw f32
    float* b2s = reinterpret_cast<float*>(dsm + 16384);   // [8]
    float* ring = reinterpret_cast<float*>(dsm + 16512);  // [3][32][512]

    const int kpos = blockIdx.x;
    const int b = blockIdx.y;
    const int qbase = blockIdx.z * 128;
    const int tid = threadIdx.x;
    const int warp = tid >> 5;     // 0..15
    const int lane = tid & 31;

    const float* relbase = relation + ((size_t)(b * NL + qbase) * NL + kpos) * NE;
    const uint32_t ring_b = smem_addr_u32(ring);

    auto issue_stage = [&](int slot, int sidx) {
        const float* base = relbase + (size_t)sidx * 32 * NL * NE;
        const uint32_t dst0 = ring_b + slot * REL_STAGE_BYTES;
#pragma unroll
        for (int i = 0; i < 8; i++) {
            int c = tid + i * 512;            // 0..4095 chunks of 16B
            int r = c >> 7;                   // stage row (128 chunks/row)
            int off = (c & 127) * 4;          // float offset in row
            CP_ASYNC_CG(dst0 + (uint32_t)c * 16, base + (size_t)r * (NL * NE) + off);
        }
        CP_ASYNC_COMMIT();
    };

    // prologue: 3 stages in flight
    issue_stage(0, 0);
    issue_stage(1, 1);
    issue_stage(2, 2);

    // wk2 raw copy + bias2 (overlaps cp.async fetch)
    {
        const float4* src = reinterpret_cast<const float4*>(
            g_wk2 + (size_t)(b * NL + kpos) * NH * NE);
        float4* dst = reinterpret_cast<float4*>(wk);
        for (int i = tid; i < NH * NE / 4; i += 512) dst[i] = src[i];
        if (tid < NH) b2s[tid] = g_bias2[(size_t)(b * NL + kpos) * NH + tid];
    }

#pragma unroll
    for (int s = 0; s < 4; ++s) {
        if (s <= 1)      { CP_ASYNC_WAIT(2); }
        else if (s == 2) { CP_ASYNC_WAIT(1); }
        else             { CP_ASYNC_WAIT(0); }
        __syncthreads();   // stage s (and wk2 on s==0) visible to all

        const float* stf = ring + (s % REL_NSLOT) * (32 * 512);
        const ulonglong2* r0p = reinterpret_cast<const ulonglong2*>(
            stf + (warp * 2 + 0) * 512);
        const ulonglong2* r1p = reinterpret_cast<const ulonglong2*>(
            stf + (warp * 2 + 1) * 512);

        unsigned long long acc[2][8];
#pragma unroll
        for (int qq = 0; qq < 2; qq++)
#pragma unroll
            for (int h = 0; h < 8; h++) acc[qq][h] = 0ull;

#pragma unroll
        for (int i128 = 0; i128 < 4; i128++) {
            const int g0 = i128 * 128 + lane * 4;
            ulonglong2 r0 = r0p[i128 * 32 + lane];
            ulonglong2 r1 = r1p[i128 * 32 + lane];
#pragma unroll
            for (int h = 0; h < 8; h++) {
                ulonglong2 w = *reinterpret_cast<const ulonglong2*>(&wk[h * NE + g0]);
                fma2(acc[0][h], r0.x, w.x);
                fma2(acc[0][h], r0.y, w.y);
                fma2(acc[1][h], r1.x, w.x);
                fma2(acc[1][h], r1.y, w.y);
            }
        }

        // vals[2i] = even-g part, vals[2i+1] = odd-g part of output i = qq*8+h
        float vals[32];
#pragma unroll
        for (int qq = 0; qq < 2; qq++)
#pragma unroll
            for (int h = 0; h < 8; h++)
                f2unpack(vals[(qq * 8 + h) * 2], vals[(qq * 8 + h) * 2 + 1], acc[qq][h]);

        // transpose-reduce: lane l ends with lane-sum of vals[l]
#pragma unroll
        for (int off = 16; off > 0; off >>= 1) {
            bool hi = (lane & off) != 0;
#pragma unroll
            for (int i = 0; i < 16; i++) {
                if (i < off) {
                    float send = hi ? vals[i] : vals[i + off];
                    float recv = __shfl_xor_sync(0xffffffffu, send, off);
                    vals[i] = (hi ? vals[i + off] : vals[i]) + recv;
                }
            }
        }
        // combine even/odd halves: output i lives at lanes (2i, 2i+1)
        float fin = vals[0] + __shfl_xor_sync(0xffffffffu, vals[0], 1);
        if ((lane & 1) == 0) {
            const int i = lane >> 1;          // 0..15
            const int qq = i >> 3;
            const int h = i & 7;
            const int q = qbase + s * 32 + warp * 2 + qq;
            float s1 = g_S1[(((size_t)b * NH + h) * NL + q) * NL + kpos];
            g_S[(((size_t)b * NL + q) * NL + kpos) * NH + h] = fin + s1 + b2s[h];
        }

        if (s == 0) {
            __syncthreads();                  // slot 0 fully consumed
            issue_stage(0, 3);
        }
    }
}

// ---------------- K5: softmax over k + write probs ----------------
__global__ void __launch_bounds__(256) k_softmax(float* __restrict__ a_out, int write_a)
{
    const int q = blockIdx.x;
    const int b = blockIdx.y;
    const int tid = threadIdx.x;
    const int warp = tid >> 5;   // = head
    const int lane = tid & 31;

    __shared__ float Ss[NL][NH + 1];   // padded

    const float* Srow = g_S + (size_t)(b * NL + q) * NL * NH;
    for (int i = tid; i < NL * NH / 4; i += 256) {
        float4 v = reinterpret_cast<const float4*>(Srow)[i];
        int idx = i * 4;
        int kk = idx >> 3, h0 = idx & 7;
        Ss[kk][h0] = v.x; Ss[kk][h0 + 1] = v.y;
        Ss[kk][h0 + 2] = v.z; Ss[kk][h0 + 3] = v.w;
    }
    __syncthreads();

    const int h = warp;
    float x[8];
#pragma unroll
    for (int i = 0; i < 8; i++) x[i] = Ss[lane + 32 * i][h];

    float m = x[0];
#pragma unroll
    for (int i = 1; i < 8; i++) m = fmaxf(m, x[i]);
#pragma unroll
    for (int off = 16; off > 0; off >>= 1)
        m = fmaxf(m, __shfl_xor_sync(0xffffffffu, m, off));

    float e[8], s = 0.f;
#pragma unroll
    for (int i = 0; i < 8; i++) { e[i] = __expf(x[i] - m); s += e[i]; }
#pragma unroll
    for (int off = 16; off > 0; off >>= 1)
        s += __shfl_xor_sync(0xffffffffu, s, off);
    float inv = 1.0f / s;

    float* Prow = g_P + (((size_t)b * NH + h) * NL + q) * NL;
#pragma unroll
    for (int i = 0; i < 8; i++) {
        float p = e[i] * inv;
        Prow[lane + 32 * i] = p;
        Ss[lane + 32 * i][h] = p;    // own column only
    }
    __syncthreads();

    if (write_a) {
        float* arow = a_out + (size_t)(b * NL + q) * NL * NH;
        int t = tid;
        float4 v0 = make_float4(Ss[t][0], Ss[t][1], Ss[t][2], Ss[t][3]);
        float4 v1 = make_float4(Ss[t][4], Ss[t][5], Ss[t][6], Ss[t][7]);
        reinterpret_cast<float4*>(arow + t * 8)[0] = v0;
        reinterpret_cast<float4*>(arow + t * 8)[1] = v1;
    }
}

// ---------------- K6: attn = P @ vp per (b,h) ----------------
__global__ void __launch_bounds__(256) k_attn()
{
    int z = blockIdx.z;           // b*NH + h
    int b = z >> 3, h = z & 7;
    const float* A = g_P + (size_t)z * NL * NL;              // L x L
    const float* Bw = g_vp + (size_t)b * NL * NE + h * ND;   // L x 64, ldb=NE
    float* C = g_attn + (size_t)b * NL * NE + h * ND;        // ldc=NE
    gemm_mma<false>(A, NL, Bw, NE, C, NE, NL, 1.0f, nullptr);
}

// ---------------- K7: out = attn @ Wo^T + bo ----------------
__global__ void __launch_bounds__(256) k_out(
    const float* __restrict__ Wo, const float* __restrict__ bo,
    float* __restrict__ out)
{
    gemm_mma<true>(g_attn, NE, Wo, NE, out, NE, NE, 1.0f, bo);
}

// ---------------- launch ----------------
extern "C" void kernel_launch(void* const* d_in, const int* in_sizes, int n_in,
                              void* d_out, int out_size)
{
    const float* query    = (const float*)d_in[0];
    const float* key      = (const float*)d_in[1];
    const float* value    = (const float*)d_in[2];
    const float* relation = (const float*)d_in[3];
    const float* Wq       = (const float*)d_in[4];
    const float* Wk       = (const float*)d_in[5];
    // d_in[6] = Wv — unused (source bug: value projected with Wq)
    const float* Wr       = (const float*)d_in[7];
    const float* br       = (const float*)d_in[8];
    const float* Wo       = (const float*)d_in[9];
    const float* bo       = (const float*)d_in[10];

    float* out = (float*)d_out;
    const int out_elems = NB * NL * NE;            // 262144
    const int a_elems   = NB * NL * NL * NH;       // 1048576
    int write_a = (out_size >= out_elems + a_elems) ? 1 : 0;
    float* a_out = out + out_elems;

    // raise dynamic-smem limit for k_rel (capture-safe: not a stream op)
    cudaFuncSetAttribute((const void*)k_rel,
                         cudaFuncAttributeMaxDynamicSharedMemorySize, REL_SMEM);

    dim3 blk(256);
    k_proj   <<<dim3(8, 4, 3),   blk>>>(query, key, value, Wq, Wk);
    k_mid    <<<dim3(8, 4, 24),  blk>>>(Wr);
    k_bias2  <<<16, 256>>>(br);
    k_rel    <<<dim3(NL, NB, 2), dim3(512), REL_SMEM>>>(relation);  // idx 3 -> profiled
    k_softmax<<<dim3(NL, NB),    blk>>>(a_out, write_a);
    k_attn   <<<dim3(1, 2, 16),  blk>>>();
    k_out    <<<dim3(8, 4, 1),   blk>>>(Wo, bo, out);
}

// round 13
// speedup vs baseline: 2.1485x; 1.1265x over previous
#include <cuda_runtime.h>
#include <cuda_bf16.h>
#include <cstdint>

// Problem constants
#define NB 2
#define NL 256
#define NE 512
#define NH 8
#define ND 64   // head dim
// scale = 1/sqrt(64) = 0.125

// ---------------- device scratch (no allocations allowed) ----------------
__device__ float g_qp[NB*NL*NE];
__device__ float g_kp[NB*NL*NE];
__device__ float g_vp[NB*NL*NE];
__device__ float g_wk2[NB*NL*NH*NE];     // [b,k,h,g], pre-scaled by 1/8
__device__ float g_bias2[NB*NL*NH];      // pre-scaled by 1/8
__device__ float g_S1[NB*NH*NL*NL];      // [b,h,q,k], pre-scaled by 1/8
__device__ float g_S[NB*NL*NL*NH];       // logits, [b,q,k,h]
__device__ float g_P[NB*NH*NL*NL];       // probs, [b,h,q,k]
__device__ float g_attn[NB*NL*NE];       // [b,q, h*64+e]

// ---------------- packed f32x2 helpers ----------------
__device__ __forceinline__ unsigned long long f2pack(float lo, float hi) {
    unsigned long long r;
    asm("mov.b64 %0, {%1, %2};" : "=l"(r) : "f"(lo), "f"(hi));
    return r;
}
__device__ __forceinline__ void f2unpack(float& lo, float& hi, unsigned long long v) {
    asm("mov.b64 {%0, %1}, %2;" : "=f"(lo), "=f"(hi) : "l"(v));
}
__device__ __forceinline__ void fma2(unsigned long long& d,
                                     unsigned long long a, unsigned long long b) {
    asm("fma.rn.f32x2 %0, %1, %2, %0;" : "+l"(d) : "l"(a), "l"(b));
}
__device__ __forceinline__ unsigned long long add2(unsigned long long a,
                                                   unsigned long long b) {
    unsigned long long r;
    asm("add.rn.f32x2 %0, %1, %2;" : "=l"(r) : "l"(a), "l"(b));
    return r;
}

// ---------------- cp.async helpers (base PTX, sm_80+) ----------------
#define CP_ASYNC_CG(dst_u32, src_ptr) \
    asm volatile("cp.async.cg.shared.global [%0], [%1], 16;" \
        :: "r"(dst_u32), "l"(src_ptr) : "memory")
#define CP_ASYNC_COMMIT() \
    asm volatile("cp.async.commit_group;" ::: "memory")
#define CP_ASYNC_WAIT(N) \
    asm volatile("cp.async.wait_group %0;" :: "n"(N) : "memory")

// ---------------- warp-mma helpers (base PTX, sm_80+: valid on sm_103) ----------------
__device__ __forceinline__ uint32_t smem_addr_u32(const void* p) {
    return (uint32_t)__cvta_generic_to_shared(p);
}
__device__ __forceinline__ void ldsm4(uint32_t* r, uint32_t a) {
    asm volatile("ldmatrix.sync.aligned.m8n8.x4.shared.b16 {%0,%1,%2,%3}, [%4];"
        : "=r"(r[0]), "=r"(r[1]), "=r"(r[2]), "=r"(r[3]) : "r"(a));
}
__device__ __forceinline__ void ldsm4t(uint32_t* r, uint32_t a) {
    asm volatile("ldmatrix.sync.aligned.m8n8.x4.trans.shared.b16 {%0,%1,%2,%3}, [%4];"
        : "=r"(r[0]), "=r"(r[1]), "=r"(r[2]), "=r"(r[3]) : "r"(a));
}
__device__ __forceinline__ void mma_bf16(float* c, const uint32_t* a, const uint32_t* b) {
    asm volatile("mma.sync.aligned.m16n8k16.row.col.f32.bf16.bf16.f32 "
        "{%0,%1,%2,%3}, {%4,%5,%6,%7}, {%8,%9}, {%0,%1,%2,%3};"
        : "+f"(c[0]), "+f"(c[1]), "+f"(c[2]), "+f"(c[3])
        : "r"(a[0]), "r"(a[1]), "r"(a[2]), "r"(a[3]), "r"(b[0]), "r"(b[1]));
}

// ---------------- GEMM v5b: bf16-split tensor-core GEMM with LDG prefetch ----------------
// C[m,n] = alpha * sum_k A[m,k]*B[k,n]   (TRANS_B: B stored [n,k])  (+bias[n])
// Block tile 128(m) x 64(n), 256 threads = 8 warps (4m x 2n), warp tile 32x32.
template<bool TRANS_B>
__device__ __forceinline__ void gemm_mma(
    const float* __restrict__ A, int lda,
    const float* __restrict__ B, int ldb,
    float* __restrict__ C, int ldc,
    int K, float alpha, const float* __restrict__ bias)
{
    constexpr int SAS = 40;                  // sA row stride (elems): 80B, 16B-aligned
    constexpr int SBR = TRANS_B ? 64 : 32;   // sB rows
    constexpr int SBS = TRANS_B ? 40 : 72;   // sB row stride (80B / 144B)
    __shared__ __nv_bfloat16 sAh[128 * SAS], sAl[128 * SAS];
    __shared__ __nv_bfloat16 sBh[SBR * SBS], sBl[SBR * SBS];

    const int tid = threadIdx.x;
    const int lane = tid & 31;
    const int wid = tid >> 5;
    const int wm = wid & 3;                  // warp m index (0..3)
    const int wn = wid >> 2;                 // warp n index (0..1)
    const int bm = blockIdx.y * 128;
    const int bn = blockIdx.x * 64;

    const uint32_t sAh_b = smem_addr_u32(sAh);
    const uint32_t sAl_b = smem_addr_u32(sAl);
    const uint32_t sBh_b = smem_addr_u32(sBh);
    const uint32_t sBl_b = smem_addr_u32(sBl);

    const int aRowL = wm * 32 + (lane & 15);          // + mt*16
    const int aColL = (lane >> 4) * 8;                // + kk
    const int bRowL = TRANS_B ? (wn * 32 + (lane & 7) + (lane >> 4) * 8)
                              : ((lane & 7) + ((lane >> 3) & 1) * 8);
    const int bColL = TRANS_B ? (((lane >> 3) & 1) * 8)
                              : (wn * 32 + (lane >> 4) * 8);

    // staging indices
    const int aSRow = tid >> 3, aSC4 = (tid & 7) * 4;
    const int bSRowN = tid >> 4, bSC4N = (tid & 15) * 4;
    const int bSRowT = tid >> 3, bSC4T = (tid & 7) * 4;

    float4 aR[4], bR[2];
    auto ldg = [&](int k0) {
#pragma unroll
        for (int i = 0; i < 4; i++)
            aR[i] = *reinterpret_cast<const float4*>(
                A + (size_t)(bm + aSRow + i * 32) * lda + k0 + aSC4);
#pragma unroll
        for (int i = 0; i < 2; i++) {
            if (!TRANS_B)
                bR[i] = *reinterpret_cast<const float4*>(
                    B + (size_t)(k0 + bSRowN + i * 16) * ldb + bn + bSC4N);
            else
                bR[i] = *reinterpret_cast<const float4*>(
                    B + (size_t)(bn + bSRowT + i * 32) * ldb + k0 + bSC4T);
        }
    };
    auto split_store = [&](__nv_bfloat16* hB, __nv_bfloat16* lB, int idx, float4 v) {
        __nv_bfloat162 h01 = __floats2bfloat162_rn(v.x, v.y);
        __nv_bfloat162 h23 = __floats2bfloat162_rn(v.z, v.w);
        float2 f01 = __bfloat1622float2(h01);
        float2 f23 = __bfloat1622float2(h23);
        __nv_bfloat162 l01 = __floats2bfloat162_rn(v.x - f01.x, v.y - f01.y);
        __nv_bfloat162 l23 = __floats2bfloat162_rn(v.z - f23.x, v.w - f23.y);
        *reinterpret_cast<__nv_bfloat162*>(&hB[idx])     = h01;
        *reinterpret_cast<__nv_bfloat162*>(&hB[idx + 2]) = h23;
        *reinterpret_cast<__nv_bfloat162*>(&lB[idx])     = l01;
        *reinterpret_cast<__nv_bfloat162*>(&lB[idx + 2]) = l23;
    };
    auto sts = [&]() {
#pragma unroll
        for (int i = 0; i < 4; i++)
            split_store(sAh, sAl, (aSRow + i * 32) * SAS + aSC4, aR[i]);
#pragma unroll
        for (int i = 0; i < 2; i++) {
            int idx = (!TRANS_B) ? ((bSRowN + i * 16) * SBS + bSC4N)
                                 : ((bSRowT + i * 32) * SBS + bSC4T);
            split_store(sBh, sBl, idx, bR[i]);
        }
    };

    float acc[2][4][4];
#pragma unroll
    for (int mt = 0; mt < 2; mt++)
#pragma unroll
        for (int nt = 0; nt < 4; nt++)
#pragma unroll
            for (int j = 0; j < 4; j++) acc[mt][nt][j] = 0.f;

    const int nchunk = K / 32;
    ldg(0);
    sts();
    __syncthreads();

    for (int c = 0; c < nchunk; ++c) {
        if (c + 1 < nchunk) ldg((c + 1) * 32);   // prefetch overlaps MMAs below

#pragma unroll
        for (int kk = 0; kk < 32; kk += 16) {
            uint32_t afr[2][4], bh[8], bl[8];
#pragma unroll
            for (int mt = 0; mt < 2; mt++) {
                uint32_t off = (uint32_t)(((aRowL + mt * 16) * SAS + aColL + kk) * 2);
                ldsm4(afr[mt], sAh_b + off);
            }
#pragma unroll
            for (int ntp = 0; ntp < 2; ntp++) {
                uint32_t off;
                if (!TRANS_B)
                    off = (uint32_t)(((bRowL + kk) * SBS + bColL + ntp * 16) * 2);
                else
                    off = (uint32_t)(((bRowL + ntp * 16) * SBS + bColL + kk) * 2);
                if (!TRANS_B) {
                    ldsm4t(&bh[ntp * 4], sBh_b + off);
                    ldsm4t(&bl[ntp * 4], sBl_b + off);
                } else {
                    ldsm4(&bh[ntp * 4], sBh_b + off);
                    ldsm4(&bl[ntp * 4], sBl_b + off);
                }
            }
#pragma unroll
            for (int mt = 0; mt < 2; mt++)
#pragma unroll
                for (int nt = 0; nt < 4; nt++) {
                    const uint32_t* bp = &bh[(nt >> 1) * 4 + (nt & 1) * 2];
                    const uint32_t* lp = &bl[(nt >> 1) * 4 + (nt & 1) * 2];
                    mma_bf16(acc[mt][nt], afr[mt], bp);
                    mma_bf16(acc[mt][nt], afr[mt], lp);
                }
#pragma unroll
            for (int mt = 0; mt < 2; mt++) {
                uint32_t off = (uint32_t)(((aRowL + mt * 16) * SAS + aColL + kk) * 2);
                ldsm4(afr[mt], sAl_b + off);
            }
#pragma unroll
            for (int mt = 0; mt < 2; mt++)
#pragma unroll
                for (int nt = 0; nt < 4; nt++)
                    mma_bf16(acc[mt][nt], afr[mt], &bh[(nt >> 1) * 4 + (nt & 1) * 2]);
        }

        if (c + 1 < nchunk) {
            __syncthreads();
            sts();
            __syncthreads();
        }
    }

    // ---- epilogue ----
    const int r0 = bm + wm * 32 + (lane >> 2);
    const int c0 = bn + wn * 32 + (lane & 3) * 2;
#pragma unroll
    for (int mt = 0; mt < 2; mt++)
#pragma unroll
        for (int nt = 0; nt < 4; nt++) {
            const int row = r0 + mt * 16;
            const int col = c0 + nt * 8;
            float2 v0, v1;
            v0.x = acc[mt][nt][0] * alpha; v0.y = acc[mt][nt][1] * alpha;
            v1.x = acc[mt][nt][2] * alpha; v1.y = acc[mt][nt][3] * alpha;
            if (bias) {
                v0.x += bias[col]; v0.y += bias[col + 1];
                v1.x += bias[col]; v1.y += bias[col + 1];
            }
            *reinterpret_cast<float2*>(C + (size_t)row * ldc + col) = v0;
            *reinterpret_cast<float2*>(C + (size_t)(row + 8) * ldc + col) = v1;
        }
}

// ---------------- K1: projections qp = query@Wq, kp = key@Wk, vp = value@Wq ----------------
__global__ void __launch_bounds__(256) k_proj(
    const float* __restrict__ q, const float* __restrict__ k,
    const float* __restrict__ v,
    const float* __restrict__ Wq, const float* __restrict__ Wk)
{
    int z = blockIdx.z;
    const float* A = (z == 0) ? q : (z == 1) ? k : v;
    const float* W = (z == 1) ? Wk : Wq;   // value uses Wq (bug preserved from source)
    float* C = (z == 0) ? g_qp : (z == 1) ? g_kp : g_vp;
    gemm_mma<false>(A, NE, W, NE, C, NE, NE, 1.0f, nullptr);
}

// ---------------- K2 (merged): wk2 (z<8), S1 (z in 8..23) ----------------
__global__ void __launch_bounds__(256) k_mid(const float* __restrict__ Wr)
{
    const int z = blockIdx.z;
    if (z < 8) {
        // Wk2[b,k,h,:] = (1/8) * kp_head(b,k,h,:) @ Wr[h*64:(h+1)*64, :]
        const int h = z;
        gemm_mma<false>(g_kp + h * ND, NE,
                        Wr + (size_t)h * ND * NE, NE,
                        g_wk2 + (size_t)h * NE, NH * NE,
                        ND, 0.125f, nullptr);
    } else {
        // S1[b,h,q,k] = (1/8) * qp_h @ kp_h^T
        if (blockIdx.x >= 4 || blockIdx.y >= 2) return;
        const int zz = z - 8;            // b*NH + h
        const int b = zz >> 3, h = zz & 7;
        gemm_mma<true>(g_qp + (size_t)b * NL * NE + h * ND, NE,
                       g_kp + (size_t)b * NL * NE + h * ND, NE,
                       g_S1 + (size_t)zz * NL * NL, NL,
                       ND, 0.125f, nullptr);
    }
}

// ---------------- K3: bias2[b,k,h] = (1/8) * dot(br_head, kp_head) ----------------
__global__ void k_bias2(const float* __restrict__ br)
{
    int idx = blockIdx.x * blockDim.x + threadIdx.x;  // NB*NL*NH = 4096
    if (idx >= NB * NL * NH) return;
    int h = idx & (NH - 1);
    int row = idx >> 3;
    float s = 0.f;
#pragma unroll 8
    for (int e = 0; e < ND; e++)
        s += br[h * ND + e] * g_kp[(size_t)row * NE + h * ND + e];
    g_bias2[idx] = s * 0.125f;
}

// ---------------- K4: relation stream v3 — g-chunk stages, persistent accs ----------------
// Block = (kpos, b, qslice of 32 rows), 256 threads = 8 warps.
// Warp w owns rows qbase + w*4 .. +3 for ALL g; stages iterate over g (4 x 128).
// Each warp cp.asyncs ONLY its own rows -> per-warp wait + syncwarp, no block
// syncs in the loop. Accumulators (4 rows x 8 heads, g-paired f32x2) persist
// across stages; ONE u64 butterfly reduce at the end.
// smem: wk2 raw 16KB @0, bias2 @16384, ring @16416: [4 stages][32 rows][128 f].
#define REL_SMEM (16416 + 4 * 32 * 128 * 4)
__global__ void __launch_bounds__(256, 2) k_rel(const float* __restrict__ relation)
{
    extern __shared__ char dsm[];
    float* wk  = reinterpret_cast<float*>(dsm);           // [8][512]
    float* b2s = reinterpret_cast<float*>(dsm + 16384);   // [8]
    float* ring = reinterpret_cast<float*>(dsm + 16416);  // [4][32][128]

    const int kpos = blockIdx.x;
    const int b = blockIdx.y;
    const int qbase = blockIdx.z * 32;
    const int tid = threadIdx.x;
    const int warp = tid >> 5;     // 0..7
    const int lane = tid & 31;

    const uint32_t ring_b = smem_addr_u32(ring);

    // per-lane source row pointers (lane covers bytes lane*16 of each 512B chunk)
    const float* rowptr[4];
#pragma unroll
    for (int j = 0; j < 4; j++)
        rowptr[j] = relation +
            ((size_t)(b * NL + qbase + warp * 4 + j) * NL + kpos) * NE + lane * 4;

    // issue all 4 stages (one commit group per stage); each warp fetches only
    // its own 4 rows' 128-float g-chunk per stage.
#pragma unroll
    for (int s = 0; s < 4; s++) {
        const uint32_t dst = ring_b + s * 16384 + (warp * 4) * 512 + lane * 16;
#pragma unroll
        for (int j = 0; j < 4; j++)
            CP_ASYNC_CG(dst + j * 512, rowptr[j] + s * 128);
        CP_ASYNC_COMMIT();
    }

    // cooperative wk2 + bias2 load (overlaps cp.async fetch)
    {
        const float4* src = reinterpret_cast<const float4*>(
            g_wk2 + (size_t)(b * NL + kpos) * NH * NE);
        float4* dst = reinterpret_cast<float4*>(wk);
        for (int i = tid; i < NH * NE / 4; i += 256) dst[i] = src[i];
        if (tid < NH) b2s[tid] = g_bias2[(size_t)(b * NL + kpos) * NH + tid];
    }
    __syncthreads();   // wk visible to all warps

    unsigned long long acc[32];    // acc[j*8+h], (even-g, odd-g) packed
#pragma unroll
    for (int i = 0; i < 32; i++) acc[i] = 0ull;

#pragma unroll
    for (int s = 0; s < 4; s++) {
        if (s == 0)      { CP_ASYNC_WAIT(3); }
        else if (s == 1) { CP_ASYNC_WAIT(2); }
        else if (s == 2) { CP_ASYNC_WAIT(1); }
        else             { CP_ASYNC_WAIT(0); }
        __syncwarp();   // all lanes' copies for stage s complete

        const float* stf = ring + s * 4096 + (warp * 4) * 128;
        ulonglong2 r[4];
#pragma unroll
        for (int j = 0; j < 4; j++)
            r[j] = *reinterpret_cast<const ulonglong2*>(stf + j * 128 + lane * 4);

        const int gofs = s * 128 + lane * 4;
#pragma unroll
        for (int h = 0; h < 8; h++) {
            ulonglong2 w = *reinterpret_cast<const ulonglong2*>(&wk[h * NE + gofs]);
#pragma unroll
            for (int j = 0; j < 4; j++) {
                fma2(acc[j * 8 + h], r[j].x, w.x);
                fma2(acc[j * 8 + h], r[j].y, w.y);
            }
        }
    }

    // single u64 butterfly transpose-reduce: lane l ends with acc[0] = total
    // for output index l (j = l>>3, h = l&7)
#pragma unroll
    for (int off = 16; off > 0; off >>= 1) {
        bool hi = (lane & off) != 0;
#pragma unroll
        for (int i = 0; i < 16; i++) {
            if (i < off) {
                unsigned long long send = hi ? acc[i] : acc[i + off];
                unsigned long long recv = __shfl_xor_sync(0xffffffffu, send, off);
                unsigned long long keep = hi ? acc[i + off] : acc[i];
                acc[i] = add2(keep, recv);
            }
        }
    }

    {
        float lo, hf;
        f2unpack(lo, hf, acc[0]);
        float fin = lo + hf;
        const int j = lane >> 3;
        const int h = lane & 7;
        const int q = qbase + warp * 4 + j;
        float s1 = g_S1[(((size_t)b * NH + h) * NL + q) * NL + kpos];
        g_S[(((size_t)b * NL + q) * NL + kpos) * NH + h] = fin + s1 + b2s[h];
    }
}

// ---------------- K5: softmax over k + write probs ----------------
__global__ void __launch_bounds__(256) k_softmax(float* __restrict__ a_out, int write_a)
{
    const int q = blockIdx.x;
    const int b = blockIdx.y;
    const int tid = threadIdx.x;
    const int warp = tid >> 5;   // = head
    const int lane = tid & 31;

    __shared__ float Ss[NL][NH + 1];   // padded

    const float* Srow = g_S + (size_t)(b * NL + q) * NL * NH;
    for (int i = tid; i < NL * NH / 4; i += 256) {
        float4 v = reinterpret_cast<const float4*>(Srow)[i];
        int idx = i * 4;
        int kk = idx >> 3, h0 = idx & 7;
        Ss[kk][h0] = v.x; Ss[kk][h0 + 1] = v.y;
        Ss[kk][h0 + 2] = v.z; Ss[kk][h0 + 3] = v.w;
    }
    __syncthreads();

    const int h = warp;
    float x[8];
#pragma unroll
    for (int i = 0; i < 8; i++) x[i] = Ss[lane + 32 * i][h];

    float m = x[0];
#pragma unroll
    for (int i = 1; i < 8; i++) m = fmaxf(m, x[i]);
#pragma unroll
    for (int off = 16; off > 0; off >>= 1)
        m = fmaxf(m, __shfl_xor_sync(0xffffffffu, m, off));

    float e[8], s = 0.f;
#pragma unroll
    for (int i = 0; i < 8; i++) { e[i] = __expf(x[i] - m); s += e[i]; }
#pragma unroll
    for (int off = 16; off > 0; off >>= 1)
        s += __shfl_xor_sync(0xffffffffu, s, off);
    float inv = 1.0f / s;

    float* Prow = g_P + (((size_t)b * NH + h) * NL + q) * NL;
#pragma unroll
    for (int i = 0; i < 8; i++) {
        float p = e[i] * inv;
        Prow[lane + 32 * i] = p;
        Ss[lane + 32 * i][h] = p;    // own column only
    }
    __syncthreads();

    if (write_a) {
        float* arow = a_out + (size_t)(b * NL + q) * NL * NH;
        int t = tid;
        float4 v0 = make_float4(Ss[t][0], Ss[t][1], Ss[t][2], Ss[t][3]);
        float4 v1 = make_float4(Ss[t][4], Ss[t][5], Ss[t][6], Ss[t][7]);
        reinterpret_cast<float4*>(arow + t * 8)[0] = v0;
        reinterpret_cast<float4*>(arow + t * 8)[1] = v1;
    }
}

// ---------------- K6: attn = P @ vp per (b,h) ----------------
__global__ void __launch_bounds__(256) k_attn()
{
    int z = blockIdx.z;           // b*NH + h
    int b = z >> 3, h = z & 7;
    const float* A = g_P + (size_t)z * NL * NL;              // L x L
    const float* Bw = g_vp + (size_t)b * NL * NE + h * ND;   // L x 64, ldb=NE
    float* C = g_attn + (size_t)b * NL * NE + h * ND;        // ldc=NE
    gemm_mma<false>(A, NL, Bw, NE, C, NE, NL, 1.0f, nullptr);
}

// ---------------- K7: out = attn @ Wo^T + bo ----------------
__global__ void __launch_bounds__(256) k_out(
    const float* __restrict__ Wo, const float* __restrict__ bo,
    float* __restrict__ out)
{
    gemm_mma<true>(g_attn, NE, Wo, NE, out, NE, NE, 1.0f, bo);
}

// ---------------- launch ----------------
extern "C" void kernel_launch(void* const* d_in, const int* in_sizes, int n_in,
                              void* d_out, int out_size)
{
    const float* query    = (const float*)d_in[0];
    const float* key      = (const float*)d_in[1];
    const float* value    = (const float*)d_in[2];
    const float* relation = (const float*)d_in[3];
    const float* Wq       = (const float*)d_in[4];
    const float* Wk       = (const float*)d_in[5];
    // d_in[6] = Wv — unused (source bug: value projected with Wq)
    const float* Wr       = (const float*)d_in[7];
    const float* br       = (const float*)d_in[8];
    const float* Wo       = (const float*)d_in[9];
    const float* bo       = (const float*)d_in[10];

    float* out = (float*)d_out;
    const int out_elems = NB * NL * NE;            // 262144
    const int a_elems   = NB * NL * NL * NH;       // 1048576
    int write_a = (out_size >= out_elems + a_elems) ? 1 : 0;
    float* a_out = out + out_elems;

    // raise dynamic-smem limit for k_rel (capture-safe: not a stream op)
    cudaFuncSetAttribute((const void*)k_rel,
                         cudaFuncAttributeMaxDynamicSharedMemorySize, REL_SMEM);

    dim3 blk(256);
    k_proj   <<<dim3(8, 4, 3),   blk>>>(query, key, value, Wq, Wk);
    k_mid    <<<dim3(8, 4, 24),  blk>>>(Wr);
    k_bias2  <<<16, 256>>>(br);
    k_rel    <<<dim3(NL, NB, 8), dim3(256), REL_SMEM>>>(relation);  // idx 3 -> profiled
    k_softmax<<<dim3(NL, NB),    blk>>>(a_out, write_a);
    k_attn   <<<dim3(1, 2, 16),  blk>>>();
    k_out    <<<dim3(8, 4, 1),   blk>>>(Wo, bo, out);
}